// round 1
// baseline (speedup 1.0000x reference)
#include <cuda_runtime.h>
#include <math.h>

#define NN 10000
#define EE 160000
#define CC 64
#define RR 32
#define CUT 5.0f

// ---------------- device scratch (static, allowed) ----------------
__device__ float g_Xn [NN * CC * 9];   // normalized node tensors (full 3x3)
__device__ float g_mix[NN * CC * 9];   // channel-mixed compact irreps [i0,a01,a02,a12,s00,s11,s01,s02,s12]
__device__ float g_msg[NN * CC * 9];   // aggregated messages (compact)
__device__ float g_af [(size_t)EE * 192]; // per-edge MLP output * cutoff

__device__ __forceinline__ float silu_f(float x) {
    return x / (1.0f + __expf(-x));
}

// ================= Kernel A: node prep + decompose + channel-mix =================
// block = node (64 threads = channels)
__global__ void k_node(const float* __restrict__ X, const float* __restrict__ Wt) {
    int n = blockIdx.x;
    int c = threadIdx.x;
    __shared__ float sp[9][CC];

    int idx = n * CC + c;
    const float* xp = X + (size_t)idx * 9;
    float t[9];
#pragma unroll
    for (int j = 0; j < 9; j++) t[j] = xp[j];
    float n2 = 0.f;
#pragma unroll
    for (int j = 0; j < 9; j++) n2 += t[j] * t[j];
    float inv = 1.0f / (n2 + 1.0f);

    float xn[9];
    float* xnp = g_Xn + (size_t)idx * 9;
#pragma unroll
    for (int j = 0; j < 9; j++) { xn[j] = t[j] * inv; xnp[j] = xn[j]; }

    float i0 = (xn[0] + xn[4] + xn[8]) * (1.0f / 3.0f);
    sp[0][c] = i0;
    sp[1][c] = 0.5f * (xn[1] - xn[3]);
    sp[2][c] = 0.5f * (xn[2] - xn[6]);
    sp[3][c] = 0.5f * (xn[5] - xn[7]);
    sp[4][c] = xn[0] - i0;
    sp[5][c] = xn[4] - i0;
    sp[6][c] = 0.5f * (xn[1] + xn[3]);
    sp[7][c] = 0.5f * (xn[2] + xn[6]);
    sp[8][c] = 0.5f * (xn[5] + xn[7]);

    // zero the message accumulator for this (n,c)
    float* mz = g_msg + (size_t)idx * 9;
#pragma unroll
    for (int j = 0; j < 9; j++) mz[j] = 0.0f;

    __syncthreads();

    // channel mixing: mix[n,l,j] = sum_k pre[n,k,j] * Wt_comp(j)[k,l]
    float acc[9];
#pragma unroll
    for (int j = 0; j < 9; j++) acc[j] = 0.f;
    for (int k = 0; k < CC; k++) {
        float w0 = Wt[          k * CC + c];
        float w1 = Wt[4096 +    k * CC + c];
        float w2 = Wt[8192 +    k * CC + c];
        acc[0] += sp[0][k] * w0;
        acc[1] += sp[1][k] * w1;
        acc[2] += sp[2][k] * w1;
        acc[3] += sp[3][k] * w1;
        acc[4] += sp[4][k] * w2;
        acc[5] += sp[5][k] * w2;
        acc[6] += sp[6][k] * w2;
        acc[7] += sp[7][k] * w2;
        acc[8] += sp[8][k] * w2;
    }
    float* mp = g_mix + (size_t)idx * 9;
#pragma unroll
    for (int j = 0; j < 9; j++) mp[j] = acc[j];
}

// ================= Kernel B: fused edge MLP (32->64->128->192, SiLU, cutoff) ==========
// smem float offsets
#define SW2 0          // 64*128   = 8192
#define SW3 8192       // 128*192  = 24576
#define SH1 32768      // 64 x 128 = 8192     [k][tid]
#define SH2 40960      // 128 x 128 = 16384   [k][tid]  (W1/b1 overlap here, dead after layer1)
#define SW1 40960      // 32*64 = 2048
#define SB1 43008      // 64
#define SB2 57344      // 128
#define SB3 57472      // 192
#define SMEM_FLOATS 57664

__global__ void __launch_bounds__(128, 1) k_mlp(
    const float* __restrict__ ea, const float* __restrict__ ew,
    const float* __restrict__ W1, const float* __restrict__ b1,
    const float* __restrict__ W2, const float* __restrict__ b2,
    const float* __restrict__ W3, const float* __restrict__ b3)
{
    extern __shared__ float sm[];
    int tid = threadIdx.x;

    // cooperative weight staging (float4)
    {
        float4* d; const float4* s;
        d = (float4*)(sm + SW2); s = (const float4*)W2;
        for (int i = tid; i < 2048; i += 128) d[i] = s[i];
        d = (float4*)(sm + SW3); s = (const float4*)W3;
        for (int i = tid; i < 6144; i += 128) d[i] = s[i];
        d = (float4*)(sm + SW1); s = (const float4*)W1;
        for (int i = tid; i < 512; i += 128) d[i] = s[i];
        if (tid < 64) sm[SB1 + tid] = b1[tid];
        sm[SB2 + tid] = b2[tid];
        for (int i = tid; i < 192; i += 128) sm[SB3 + i] = b3[i];
    }
    __syncthreads();

    int e = blockIdx.x * 128 + tid;
    const float* ap = ea + (size_t)e * RR;
    float acc[64];

    // ---- layer 1: 32 -> 64 ----
#pragma unroll
    for (int o = 0; o < 64; o++) acc[o] = sm[SB1 + o];
    for (int r = 0; r < 32; r++) {
        float x = __ldg(ap + r);
        const float4* wr = (const float4*)(sm + SW1 + r * 64);
#pragma unroll
        for (int q = 0; q < 16; q++) {
            float4 w = wr[q];
            acc[4*q+0] += x * w.x; acc[4*q+1] += x * w.y;
            acc[4*q+2] += x * w.z; acc[4*q+3] += x * w.w;
        }
    }
#pragma unroll
    for (int o = 0; o < 64; o++) sm[SH1 + o * 128 + tid] = silu_f(acc[o]);
    __syncthreads();   // all W1/b1 reads done before h2 overwrites that region

    // ---- layer 2: 64 -> 128 (2 output chunks of 64) ----
#pragma unroll 1
    for (int oc = 0; oc < 2; oc++) {
#pragma unroll
        for (int o = 0; o < 64; o++) acc[o] = sm[SB2 + oc * 64 + o];
        for (int k = 0; k < 64; k++) {
            float x = sm[SH1 + k * 128 + tid];
            const float4* wr = (const float4*)(sm + SW2 + k * 128 + oc * 64);
#pragma unroll
            for (int q = 0; q < 16; q++) {
                float4 w = wr[q];
                acc[4*q+0] += x * w.x; acc[4*q+1] += x * w.y;
                acc[4*q+2] += x * w.z; acc[4*q+3] += x * w.w;
            }
        }
#pragma unroll
        for (int o = 0; o < 64; o++) sm[SH2 + (oc * 64 + o) * 128 + tid] = silu_f(acc[o]);
    }

    // ---- cutoff ----
    float wgt = ew[e];
    float Cw = (wgt < CUT) ? 0.5f * (cosf(wgt * (float)(M_PI / 5.0)) + 1.0f) : 0.0f;

    // ---- layer 3: 128 -> 192 (3 output chunks of 64) ----
    float* op = g_af + (size_t)e * 192;
#pragma unroll 1
    for (int oc = 0; oc < 3; oc++) {
#pragma unroll
        for (int o = 0; o < 64; o++) acc[o] = sm[SB3 + oc * 64 + o];
        for (int k = 0; k < 128; k++) {
            float x = sm[SH2 + k * 128 + tid];
            const float4* wr = (const float4*)(sm + SW3 + k * 192 + oc * 64);
#pragma unroll
            for (int q = 0; q < 16; q++) {
                float4 w = wr[q];
                acc[4*q+0] += x * w.x; acc[4*q+1] += x * w.y;
                acc[4*q+2] += x * w.z; acc[4*q+3] += x * w.w;
            }
        }
        float4* o4 = (float4*)(op + oc * 64);
#pragma unroll
        for (int q = 0; q < 16; q++) {
            float4 v;
            v.x = silu_f(acc[4*q+0]) * Cw;
            v.y = silu_f(acc[4*q+1]) * Cw;
            v.z = silu_f(acc[4*q+2]) * Cw;
            v.w = silu_f(acc[4*q+3]) * Cw;
            o4[q] = v;
        }
    }
}

// ================= Kernel C: gather + scatter-add messages (compact irreps) =============
__global__ void k_msg(const int* __restrict__ ei) {
    int idx = blockIdx.x * 256 + threadIdx.x;   // E*64 threads
    int e = idx >> 6;
    int c = idx & 63;
    int src = __ldg(ei + e);
    int dst = __ldg(ei + EE + e);
    const float* a = g_af + (size_t)e * 192 + c * 3;
    const float* m = g_mix + (size_t)(dst * CC + c) * 9;
    float a0 = a[0], a1 = a[1], a2 = a[2];
    float* o = g_msg + (size_t)(src * CC + c) * 9;
    atomicAdd(o + 0, a0 * m[0]);
    atomicAdd(o + 1, a1 * m[1]);
    atomicAdd(o + 2, a1 * m[2]);
    atomicAdd(o + 3, a1 * m[3]);
    atomicAdd(o + 4, a2 * m[4]);
    atomicAdd(o + 5, a2 * m[5]);
    atomicAdd(o + 6, a2 * m[6]);
    atomicAdd(o + 7, a2 * m[7]);
    atomicAdd(o + 8, a2 * m[8]);
}

// ================= Kernel D: combine, second decomposition+mix, output ==================
__global__ void k_out(const float* __restrict__ Wt, float* __restrict__ out) {
    int n = blockIdx.x;
    int c = threadIdx.x;
    __shared__ float sp[9][CC];

    int idx = n * CC + c;
    const float* mgp = g_msg + (size_t)idx * 9;
    const float* mxp = g_mix + (size_t)idx * 9;
    float m9[9], y9[9];
#pragma unroll
    for (int j = 0; j < 9; j++) { m9[j] = mgp[j]; y9[j] = mxp[j]; }

    // rebuild full 3x3 tensors from compact [i0,a01,a02,a12,s00,s11,s01,s02,s12]
    float Mg[3][3] = {
        { m9[0]+m9[4],  m9[1]+m9[6],  m9[2]+m9[7] },
        { m9[6]-m9[1],  m9[0]+m9[5],  m9[3]+m9[8] },
        { m9[7]-m9[2],  m9[8]-m9[3],  m9[0]-m9[4]-m9[5] }
    };
    float Yf[3][3] = {
        { y9[0]+y9[4],  y9[1]+y9[6],  y9[2]+y9[7] },
        { y9[6]-y9[1],  y9[0]+y9[5],  y9[3]+y9[8] },
        { y9[7]-y9[2],  y9[8]-y9[3],  y9[0]-y9[4]-y9[5] }
    };

    // M = Mg@Y + Y@Mg
    float M[3][3];
#pragma unroll
    for (int i = 0; i < 3; i++)
#pragma unroll
        for (int j = 0; j < 3; j++) {
            float s = 0.f;
#pragma unroll
            for (int k = 0; k < 3; k++)
                s += Mg[i][k] * Yf[k][j] + Yf[i][k] * Mg[k][j];
            M[i][j] = s;
        }

    float tn = 0.f;
#pragma unroll
    for (int i = 0; i < 3; i++)
#pragma unroll
        for (int j = 0; j < 3; j++) tn += M[i][j] * M[i][j];
    float inv = 1.0f / (tn + 1.0f);

    float i0 = (M[0][0] + M[1][1] + M[2][2]) * (1.0f / 3.0f);
    sp[0][c] = i0 * inv;
    sp[1][c] = 0.5f * (M[0][1] - M[1][0]) * inv;
    sp[2][c] = 0.5f * (M[0][2] - M[2][0]) * inv;
    sp[3][c] = 0.5f * (M[1][2] - M[2][1]) * inv;
    sp[4][c] = (M[0][0] - i0) * inv;
    sp[5][c] = (M[1][1] - i0) * inv;
    sp[6][c] = 0.5f * (M[0][1] + M[1][0]) * inv;
    sp[7][c] = 0.5f * (M[0][2] + M[2][0]) * inv;
    sp[8][c] = 0.5f * (M[1][2] + M[2][1]) * inv;
    __syncthreads();

    float acc[9];
#pragma unroll
    for (int j = 0; j < 9; j++) acc[j] = 0.f;
    for (int k = 0; k < CC; k++) {
        float w3 = Wt[3*4096 + k * CC + c];
        float w4 = Wt[4*4096 + k * CC + c];
        float w5 = Wt[5*4096 + k * CC + c];
        acc[0] += sp[0][k] * w3;
        acc[1] += sp[1][k] * w4;
        acc[2] += sp[2][k] * w4;
        acc[3] += sp[3][k] * w4;
        acc[4] += sp[4][k] * w5;
        acc[5] += sp[5][k] * w5;
        acc[6] += sp[6][k] * w5;
        acc[7] += sp[7][k] * w5;
        acc[8] += sp[8][k] * w5;
    }

    // dX full
    float D[3][3] = {
        { acc[0]+acc[4],  acc[1]+acc[6],  acc[2]+acc[7] },
        { acc[6]-acc[1],  acc[0]+acc[5],  acc[3]+acc[8] },
        { acc[7]-acc[2],  acc[8]-acc[3],  acc[0]-acc[4]-acc[5] }
    };
    float D2[3][3];
#pragma unroll
    for (int i = 0; i < 3; i++)
#pragma unroll
        for (int j = 0; j < 3; j++) {
            float s = 0.f;
#pragma unroll
            for (int k = 0; k < 3; k++) s += D[i][k] * D[k][j];
            D2[i][j] = s;
        }

    const float* xnp = g_Xn + (size_t)idx * 9;
    float* op = out + (size_t)idx * 9;
#pragma unroll
    for (int i = 0; i < 3; i++)
#pragma unroll
        for (int j = 0; j < 3; j++)
            op[3*i+j] = xnp[3*i+j] + D[i][j] + D2[i][j];
}

// ======================= launch =======================
extern "C" void kernel_launch(void* const* d_in, const int* in_sizes, int n_in,
                              void* d_out, int out_size) {
    const float* X  = (const float*)d_in[0];
    const int*   ei = (const int*)  d_in[1];
    const float* ew = (const float*)d_in[2];
    const float* ea = (const float*)d_in[3];
    const float* W1 = (const float*)d_in[4];
    const float* b1 = (const float*)d_in[5];
    const float* W2 = (const float*)d_in[6];
    const float* b2 = (const float*)d_in[7];
    const float* W3 = (const float*)d_in[8];
    const float* b3 = (const float*)d_in[9];
    const float* Wt = (const float*)d_in[10];

    const int smem_bytes = SMEM_FLOATS * 4;   // 230656
    cudaFuncSetAttribute(k_mlp, cudaFuncAttributeMaxDynamicSharedMemorySize, smem_bytes);

    k_node<<<NN, CC>>>(X, Wt);
    k_mlp<<<EE / 128, 128, smem_bytes>>>(ea, ew, W1, b1, W2, b2, W3, b3);
    k_msg<<<(EE * 64) / 256, 256>>>(ei);
    k_out<<<NN, CC>>>(Wt, (float*)d_out);
}

// round 3
// speedup vs baseline: 1.4522x; 1.4522x over previous
#include <cuda_runtime.h>
#include <math.h>

#define NN 10000
#define EE 160000
#define CC 64
#define RR 32
#define CUT 5.0f
#define NC (NN * CC)          // 640000

// ---------------- device scratch ----------------
__device__ float  g_Xn [NN * CC * 9];      // normalized node tensors (full 3x3)
__device__ float4 g_mixv[3 * NC];          // mixed irreps, SoA chunks: [k][n*64+c]
__device__ float4 g_msgv[3 * NC];          // aggregated messages, same layout
__device__ float  g_af [(size_t)EE * 192]; // per-edge MLP output * cutoff
// CSR by src
__device__ int  g_cnt[NN];
__device__ int  g_off[NN + 1];
__device__ int2 g_el [EE];                 // {edge id, dst}

__device__ __forceinline__ float silu_f(float x) { return x / (1.0f + __expf(-x)); }

// packed f32x2 helpers
#define FMA2(d, a, b, c) asm("fma.rn.f32x2 %0, %1, %2, %3;" : "=l"(d) : "l"(a), "l"(b), "l"(c))
#define PACK2(d, lo, hi) asm("mov.b64 %0, {%1, %2};" : "=l"(d) : "r"(lo), "r"(hi))
#define UNPACK2(lo, hi, v) asm("mov.b64 {%0, %1}, %2;" : "=r"(lo), "=r"(hi) : "l"(v))

// ================= Kernel A: node prep + decompose + channel-mix (4 nodes/block) ======
__global__ void k_node(const float* __restrict__ X, const float* __restrict__ Wt) {
    int tid = threadIdx.x;
    int nl = tid >> 6, c = tid & 63;
    int n = blockIdx.x * 4 + nl;
    __shared__ float sp[4][9][CC];

    if (tid < 4) g_cnt[blockIdx.x * 4 + tid] = 0;   // zero CSR histogram

    int idx = n * CC + c;
    const float* xp = X + (size_t)idx * 9;
    float t[9];
#pragma unroll
    for (int j = 0; j < 9; j++) t[j] = xp[j];
    float n2 = 0.f;
#pragma unroll
    for (int j = 0; j < 9; j++) n2 += t[j] * t[j];
    float inv = 1.0f / (n2 + 1.0f);

    float xn[9];
    float* xnp = g_Xn + (size_t)idx * 9;
#pragma unroll
    for (int j = 0; j < 9; j++) { xn[j] = t[j] * inv; xnp[j] = xn[j]; }

    float i0 = (xn[0] + xn[4] + xn[8]) * (1.0f / 3.0f);
    sp[nl][0][c] = i0;
    sp[nl][1][c] = 0.5f * (xn[1] - xn[3]);
    sp[nl][2][c] = 0.5f * (xn[2] - xn[6]);
    sp[nl][3][c] = 0.5f * (xn[5] - xn[7]);
    sp[nl][4][c] = xn[0] - i0;
    sp[nl][5][c] = xn[4] - i0;
    sp[nl][6][c] = 0.5f * (xn[1] + xn[3]);
    sp[nl][7][c] = 0.5f * (xn[2] + xn[6]);
    sp[nl][8][c] = 0.5f * (xn[5] + xn[7]);
    __syncthreads();

    float acc[9];
#pragma unroll
    for (int j = 0; j < 9; j++) acc[j] = 0.f;
    for (int k = 0; k < CC; k++) {
        float w0 = __ldg(Wt +        k * CC + c);
        float w1 = __ldg(Wt + 4096 + k * CC + c);
        float w2 = __ldg(Wt + 8192 + k * CC + c);
        acc[0] += sp[nl][0][k] * w0;
        acc[1] += sp[nl][1][k] * w1;
        acc[2] += sp[nl][2][k] * w1;
        acc[3] += sp[nl][3][k] * w1;
        acc[4] += sp[nl][4][k] * w2;
        acc[5] += sp[nl][5][k] * w2;
        acc[6] += sp[nl][6][k] * w2;
        acc[7] += sp[nl][7][k] * w2;
        acc[8] += sp[nl][8][k] * w2;
    }
    g_mixv[idx]          = make_float4(acc[0], acc[1], acc[2], acc[3]);
    g_mixv[NC + idx]     = make_float4(acc[4], acc[5], acc[6], acc[7]);
    g_mixv[2 * NC + idx] = make_float4(acc[8], 0.f, 0.f, 0.f);
}

// ================= CSR build =================
__global__ void k_hist(const int* __restrict__ ei) {
    int e = blockIdx.x * 256 + threadIdx.x;
    if (e < EE) atomicAdd(&g_cnt[__ldg(ei + e)], 1);
}

__global__ void k_scan() {    // single block, 1024 threads
    int t = threadIdx.x;
    int base = t * 10;
    int loc[10];
    int s = 0;
#pragma unroll
    for (int i = 0; i < 10; i++) {
        int nn = base + i;
        int v = (nn < NN) ? g_cnt[nn] : 0;
        loc[i] = s; s += v;
    }
    __shared__ int smv[1024];
    smv[t] = s;
    __syncthreads();
    for (int off = 1; off < 1024; off <<= 1) {
        int v = (t >= off) ? smv[t - off] : 0;
        __syncthreads();
        smv[t] += v;
        __syncthreads();
    }
    int pre = (t > 0) ? smv[t - 1] : 0;
#pragma unroll
    for (int i = 0; i < 10; i++) {
        int nn = base + i;
        if (nn < NN) { int o = pre + loc[i]; g_off[nn] = o; g_cnt[nn] = o; }
    }
    if (t == 1023) g_off[NN] = smv[1023];
}

__global__ void k_fill(const int* __restrict__ ei) {
    int e = blockIdx.x * 256 + threadIdx.x;
    if (e < EE) {
        int src = __ldg(ei + e);
        int dst = __ldg(ei + EE + e);
        int pos = atomicAdd(&g_cnt[src], 1);
        g_el[pos] = make_int2(e, dst);
    }
}

// ================= Kernel B: fused edge MLP with f32x2 ==========
#define SW2 0          // 64*128   = 8192
#define SW3 8192       // 128*192  = 24576
#define SH1 32768      // 64 x 128 = 8192     [k][tid]  (first 4096 used to stage ea)
#define SH2 40960      // 128 x 128 = 16384   [k][tid]  (W1/b1 overlap, dead after layer1)
#define SW1 40960      // 32*64 = 2048
#define SB1 43008      // 64
#define SB2 57344      // 128
#define SB3 57472      // 192
#define SMEM_FLOATS 57664

__global__ void __launch_bounds__(128, 1) k_mlp(
    const float* __restrict__ ea, const float* __restrict__ ew,
    const float* __restrict__ W1, const float* __restrict__ b1,
    const float* __restrict__ W2, const float* __restrict__ b2,
    const float* __restrict__ W3, const float* __restrict__ b3)
{
    extern __shared__ float sm[];
    int tid = threadIdx.x;

    // stage weights + this block's edge_attr (coalesced)
    {
        float4* d; const float4* s;
        d = (float4*)(sm + SW2); s = (const float4*)W2;
        for (int i = tid; i < 2048; i += 128) d[i] = s[i];
        d = (float4*)(sm + SW3); s = (const float4*)W3;
        for (int i = tid; i < 6144; i += 128) d[i] = s[i];
        d = (float4*)(sm + SW1); s = (const float4*)W1;
        for (int i = tid; i < 512; i += 128) d[i] = s[i];
        if (tid < 64) sm[SB1 + tid] = b1[tid];
        sm[SB2 + tid] = b2[tid];
        for (int i = tid; i < 192; i += 128) sm[SB3 + i] = b3[i];
        // edge_attr: [128 edges][32] -> sm[SH1 + r*128 + e_local]
        const float4* g = (const float4*)(ea + (size_t)blockIdx.x * 128 * 32);
        for (int i = tid; i < 1024; i += 128) {
            float4 v = g[i];
            int el = i >> 3, r0 = (i & 7) * 4;
            sm[SH1 + (r0 + 0) * 128 + el] = v.x;
            sm[SH1 + (r0 + 1) * 128 + el] = v.y;
            sm[SH1 + (r0 + 2) * 128 + el] = v.z;
            sm[SH1 + (r0 + 3) * 128 + el] = v.w;
        }
    }
    __syncthreads();

    int e = blockIdx.x * 128 + tid;
    unsigned long long acc2[32];   // 32 packed pairs = 64 outputs

    // ---- layer 1: 32 -> 64 ----
    {
        const unsigned long long* bb = (const unsigned long long*)(sm + SB1);
#pragma unroll
        for (int j = 0; j < 32; j++) acc2[j] = bb[j];
        for (int r = 0; r < 32; r++) {
            float x = sm[SH1 + r * 128 + tid];
            unsigned long long xx; unsigned xb = __float_as_uint(x);
            PACK2(xx, xb, xb);
            const ulonglong2* wr = (const ulonglong2*)(sm + SW1 + r * 64);
#pragma unroll
            for (int q = 0; q < 16; q++) {
                ulonglong2 w = wr[q];
                FMA2(acc2[2 * q],     xx, w.x, acc2[2 * q]);
                FMA2(acc2[2 * q + 1], xx, w.y, acc2[2 * q + 1]);
            }
        }
        // h1 -> SH1 [o][tid] (column-private overwrite of staged ea: safe)
#pragma unroll
        for (int j = 0; j < 32; j++) {
            unsigned lo, hi; UNPACK2(lo, hi, acc2[j]);
            sm[SH1 + (2 * j)     * 128 + tid] = silu_f(__uint_as_float(lo));
            sm[SH1 + (2 * j + 1) * 128 + tid] = silu_f(__uint_as_float(hi));
        }
    }
    __syncthreads();   // W1/b1 region about to be overwritten by h2

    // ---- layer 2: 64 -> 128 ----
#pragma unroll 1
    for (int oc = 0; oc < 2; oc++) {
        const unsigned long long* bb = (const unsigned long long*)(sm + SB2 + oc * 64);
#pragma unroll
        for (int j = 0; j < 32; j++) acc2[j] = bb[j];
        for (int k = 0; k < 64; k++) {
            float x = sm[SH1 + k * 128 + tid];
            unsigned long long xx; unsigned xb = __float_as_uint(x);
            PACK2(xx, xb, xb);
            const ulonglong2* wr = (const ulonglong2*)(sm + SW2 + k * 128 + oc * 64);
#pragma unroll
            for (int q = 0; q < 16; q++) {
                ulonglong2 w = wr[q];
                FMA2(acc2[2 * q],     xx, w.x, acc2[2 * q]);
                FMA2(acc2[2 * q + 1], xx, w.y, acc2[2 * q + 1]);
            }
        }
#pragma unroll
        for (int j = 0; j < 32; j++) {
            unsigned lo, hi; UNPACK2(lo, hi, acc2[j]);
            sm[SH2 + (oc * 64 + 2 * j)     * 128 + tid] = silu_f(__uint_as_float(lo));
            sm[SH2 + (oc * 64 + 2 * j + 1) * 128 + tid] = silu_f(__uint_as_float(hi));
        }
    }

    // ---- cutoff ----
    float wgt = __ldg(ew + e);
    float Cw = (wgt < CUT) ? 0.5f * (cosf(wgt * (float)(M_PI / 5.0)) + 1.0f) : 0.0f;

    // ---- layer 3: 128 -> 192 ----
    float* op = g_af + (size_t)e * 192;
#pragma unroll 1
    for (int oc = 0; oc < 3; oc++) {
        const unsigned long long* bb = (const unsigned long long*)(sm + SB3 + oc * 64);
#pragma unroll
        for (int j = 0; j < 32; j++) acc2[j] = bb[j];
        for (int k = 0; k < 128; k++) {
            float x = sm[SH2 + k * 128 + tid];
            unsigned long long xx; unsigned xb = __float_as_uint(x);
            PACK2(xx, xb, xb);
            const ulonglong2* wr = (const ulonglong2*)(sm + SW3 + k * 192 + oc * 64);
#pragma unroll
            for (int q = 0; q < 16; q++) {
                ulonglong2 w = wr[q];
                FMA2(acc2[2 * q],     xx, w.x, acc2[2 * q]);
                FMA2(acc2[2 * q + 1], xx, w.y, acc2[2 * q + 1]);
            }
        }
        float4* o4 = (float4*)(op + oc * 64);
#pragma unroll
        for (int t = 0; t < 16; t++) {
            unsigned l0, h0, l1, h1;
            UNPACK2(l0, h0, acc2[2 * t]);
            UNPACK2(l1, h1, acc2[2 * t + 1]);
            float4 v;
            v.x = silu_f(__uint_as_float(l0)) * Cw;
            v.y = silu_f(__uint_as_float(h0)) * Cw;
            v.z = silu_f(__uint_as_float(l1)) * Cw;
            v.w = silu_f(__uint_as_float(h1)) * Cw;
            o4[t] = v;
        }
    }
}

// ================= Kernel C: CSR gather + accumulate (no atomics) =============
__global__ void k_msg(void) {
    int n = blockIdx.x;
    int c = threadIdx.x;
    int i0 = g_off[n], i1 = g_off[n + 1];
    float4 a0v = make_float4(0.f, 0.f, 0.f, 0.f);
    float4 a1v = make_float4(0.f, 0.f, 0.f, 0.f);
    float  a2v = 0.f;
    int2 el;
    if (i0 < i1) el = __ldg(&g_el[i0]);
    for (int i = i0; i < i1; i++) {
        int2 cur = el;
        if (i + 1 < i1) el = __ldg(&g_el[i + 1]);
        const float* ap = g_af + (size_t)cur.x * 192 + c * 3;
        float a0 = __ldg(ap), a1 = __ldg(ap + 1), a2 = __ldg(ap + 2);
        int mi = cur.y * CC + c;
        float4 m0 = __ldg(&g_mixv[mi]);
        float4 m1 = __ldg(&g_mixv[NC + mi]);
        float4 m2 = __ldg(&g_mixv[2 * NC + mi]);
        a0v.x += a0 * m0.x; a0v.y += a1 * m0.y; a0v.z += a1 * m0.z; a0v.w += a1 * m0.w;
        a1v.x += a2 * m1.x; a1v.y += a2 * m1.y; a1v.z += a2 * m1.z; a1v.w += a2 * m1.w;
        a2v   += a2 * m2.x;
    }
    int idx = n * CC + c;
    g_msgv[idx]          = a0v;
    g_msgv[NC + idx]     = a1v;
    g_msgv[2 * NC + idx] = make_float4(a2v, 0.f, 0.f, 0.f);
}

// ================= Kernel D: combine, second decomposition+mix, output (4 nodes/block) ==
__global__ void k_out(const float* __restrict__ Wt, float* __restrict__ out) {
    int tid = threadIdx.x;
    int nl = tid >> 6, c = tid & 63;
    int n = blockIdx.x * 4 + nl;
    __shared__ float sp[4][9][CC];

    int idx = n * CC + c;
    float4 g0 = g_msgv[idx], g1 = g_msgv[NC + idx], g2 = g_msgv[2 * NC + idx];
    float4 y0 = g_mixv[idx], y1 = g_mixv[NC + idx], y2 = g_mixv[2 * NC + idx];
    float m9[9] = { g0.x, g0.y, g0.z, g0.w, g1.x, g1.y, g1.z, g1.w, g2.x };
    float y9[9] = { y0.x, y0.y, y0.z, y0.w, y1.x, y1.y, y1.z, y1.w, y2.x };

    float Mg[3][3] = {
        { m9[0]+m9[4],  m9[1]+m9[6],  m9[2]+m9[7] },
        { m9[6]-m9[1],  m9[0]+m9[5],  m9[3]+m9[8] },
        { m9[7]-m9[2],  m9[8]-m9[3],  m9[0]-m9[4]-m9[5] }
    };
    float Yf[3][3] = {
        { y9[0]+y9[4],  y9[1]+y9[6],  y9[2]+y9[7] },
        { y9[6]-y9[1],  y9[0]+y9[5],  y9[3]+y9[8] },
        { y9[7]-y9[2],  y9[8]-y9[3],  y9[0]-y9[4]-y9[5] }
    };

    float M[3][3];
#pragma unroll
    for (int i = 0; i < 3; i++)
#pragma unroll
        for (int j = 0; j < 3; j++) {
            float s = 0.f;
#pragma unroll
            for (int k = 0; k < 3; k++)
                s += Mg[i][k] * Yf[k][j] + Yf[i][k] * Mg[k][j];
            M[i][j] = s;
        }

    float tn = 0.f;
#pragma unroll
    for (int i = 0; i < 3; i++)
#pragma unroll
        for (int j = 0; j < 3; j++) tn += M[i][j] * M[i][j];
    float inv = 1.0f / (tn + 1.0f);

    float i0 = (M[0][0] + M[1][1] + M[2][2]) * (1.0f / 3.0f);
    sp[nl][0][c] = i0 * inv;
    sp[nl][1][c] = 0.5f * (M[0][1] - M[1][0]) * inv;
    sp[nl][2][c] = 0.5f * (M[0][2] - M[2][0]) * inv;
    sp[nl][3][c] = 0.5f * (M[1][2] - M[2][1]) * inv;
    sp[nl][4][c] = (M[0][0] - i0) * inv;
    sp[nl][5][c] = (M[1][1] - i0) * inv;
    sp[nl][6][c] = 0.5f * (M[0][1] + M[1][0]) * inv;
    sp[nl][7][c] = 0.5f * (M[0][2] + M[2][0]) * inv;
    sp[nl][8][c] = 0.5f * (M[1][2] + M[2][1]) * inv;
    __syncthreads();

    float acc[9];
#pragma unroll
    for (int j = 0; j < 9; j++) acc[j] = 0.f;
    for (int k = 0; k < CC; k++) {
        float w3 = __ldg(Wt + 3*4096 + k * CC + c);
        float w4 = __ldg(Wt + 4*4096 + k * CC + c);
        float w5 = __ldg(Wt + 5*4096 + k * CC + c);
        acc[0] += sp[nl][0][k] * w3;
        acc[1] += sp[nl][1][k] * w4;
        acc[2] += sp[nl][2][k] * w4;
        acc[3] += sp[nl][3][k] * w4;
        acc[4] += sp[nl][4][k] * w5;
        acc[5] += sp[nl][5][k] * w5;
        acc[6] += sp[nl][6][k] * w5;
        acc[7] += sp[nl][7][k] * w5;
        acc[8] += sp[nl][8][k] * w5;
    }

    float D[3][3] = {
        { acc[0]+acc[4],  acc[1]+acc[6],  acc[2]+acc[7] },
        { acc[6]-acc[1],  acc[0]+acc[5],  acc[3]+acc[8] },
        { acc[7]-acc[2],  acc[8]-acc[3],  acc[0]-acc[4]-acc[5] }
    };
    float D2[3][3];
#pragma unroll
    for (int i = 0; i < 3; i++)
#pragma unroll
        for (int j = 0; j < 3; j++) {
            float s = 0.f;
#pragma unroll
            for (int k = 0; k < 3; k++) s += D[i][k] * D[k][j];
            D2[i][j] = s;
        }

    const float* xnp = g_Xn + (size_t)idx * 9;
    float* op = out + (size_t)idx * 9;
#pragma unroll
    for (int i = 0; i < 3; i++)
#pragma unroll
        for (int j = 0; j < 3; j++)
            op[3*i+j] = xnp[3*i+j] + D[i][j] + D2[i][j];
}

// ======================= launch =======================
extern "C" void kernel_launch(void* const* d_in, const int* in_sizes, int n_in,
                              void* d_out, int out_size) {
    const float* X  = (const float*)d_in[0];
    const int*   ei = (const int*)  d_in[1];
    const float* ew = (const float*)d_in[2];
    const float* ea = (const float*)d_in[3];
    const float* W1 = (const float*)d_in[4];
    const float* b1 = (const float*)d_in[5];
    const float* W2 = (const float*)d_in[6];
    const float* b2 = (const float*)d_in[7];
    const float* W3 = (const float*)d_in[8];
    const float* b3 = (const float*)d_in[9];
    const float* Wt = (const float*)d_in[10];

    const int smem_bytes = SMEM_FLOATS * 4;
    cudaFuncSetAttribute(k_mlp, cudaFuncAttributeMaxDynamicSharedMemorySize, smem_bytes);

    k_node<<<NN / 4, 256>>>(X, Wt);
    k_hist<<<(EE + 255) / 256, 256>>>(ei);
    k_scan<<<1, 1024>>>();
    k_fill<<<(EE + 255) / 256, 256>>>(ei);
    k_mlp<<<EE / 128, 128, smem_bytes>>>(ea, ew, W1, b1, W2, b2, W3, b3);
    k_msg<<<NN, CC>>>();
    k_out<<<NN / 4, 256>>>(Wt, (float*)d_out);
}

// round 7
// speedup vs baseline: 1.6825x; 1.1586x over previous
#include <cuda_runtime.h>
#include <math.h>
#include <stdint.h>

#define NN 10000
#define EE 160000
#define CC 64
#define RR 32
#define CUT 5.0f
#define NC (NN * CC)

// ---------------- device scratch ----------------
__device__ float  g_Xn [NN * CC * 9];
__device__ float4 g_mixv[3 * NC];
__device__ float4 g_msgv[3 * NC];
__device__ float  g_af [(size_t)EE * 192];
__device__ int  g_cnt[NN];
__device__ int  g_off[NN + 1];
__device__ int2 g_el [EE];

__device__ __forceinline__ float silu_f(float x) { return x / (1.0f + __expf(-x)); }

// packed f32x2 helpers (supported on sm_100 base — proven in R3)
#define FMA2(d, a, b, c) asm("fma.rn.f32x2 %0, %1, %2, %3;" : "=l"(d) : "l"(a), "l"(b), "l"(c))
#define PACK2(d, lo, hi) asm("mov.b64 %0, {%1, %2};" : "=l"(d) : "r"(lo), "r"(hi))
#define UNPACK2(lo, hi, v) asm("mov.b64 {%0, %1}, %2;" : "=r"(lo), "=r"(hi) : "l"(v))

// ================= Kernel A: node prep + decompose + channel-mix (4 nodes/block) ======
__global__ void k_node(const float* __restrict__ X, const float* __restrict__ Wt) {
    int tid = threadIdx.x;
    int nl = tid >> 6, c = tid & 63;
    int n = blockIdx.x * 4 + nl;
    __shared__ float sp[4][9][CC];

    if (tid < 4) g_cnt[blockIdx.x * 4 + tid] = 0;

    int idx = n * CC + c;
    const float* xp = X + (size_t)idx * 9;
    float t[9];
#pragma unroll
    for (int j = 0; j < 9; j++) t[j] = xp[j];
    float n2 = 0.f;
#pragma unroll
    for (int j = 0; j < 9; j++) n2 += t[j] * t[j];
    float inv = 1.0f / (n2 + 1.0f);

    float xn[9];
    float* xnp = g_Xn + (size_t)idx * 9;
#pragma unroll
    for (int j = 0; j < 9; j++) { xn[j] = t[j] * inv; xnp[j] = xn[j]; }

    float i0 = (xn[0] + xn[4] + xn[8]) * (1.0f / 3.0f);
    sp[nl][0][c] = i0;
    sp[nl][1][c] = 0.5f * (xn[1] - xn[3]);
    sp[nl][2][c] = 0.5f * (xn[2] - xn[6]);
    sp[nl][3][c] = 0.5f * (xn[5] - xn[7]);
    sp[nl][4][c] = xn[0] - i0;
    sp[nl][5][c] = xn[4] - i0;
    sp[nl][6][c] = 0.5f * (xn[1] + xn[3]);
    sp[nl][7][c] = 0.5f * (xn[2] + xn[6]);
    sp[nl][8][c] = 0.5f * (xn[5] + xn[7]);
    __syncthreads();

    float acc[9];
#pragma unroll
    for (int j = 0; j < 9; j++) acc[j] = 0.f;
    for (int k = 0; k < CC; k++) {
        float w0 = __ldg(Wt +        k * CC + c);
        float w1 = __ldg(Wt + 4096 + k * CC + c);
        float w2 = __ldg(Wt + 8192 + k * CC + c);
        acc[0] += sp[nl][0][k] * w0;
        acc[1] += sp[nl][1][k] * w1;
        acc[2] += sp[nl][2][k] * w1;
        acc[3] += sp[nl][3][k] * w1;
        acc[4] += sp[nl][4][k] * w2;
        acc[5] += sp[nl][5][k] * w2;
        acc[6] += sp[nl][6][k] * w2;
        acc[7] += sp[nl][7][k] * w2;
        acc[8] += sp[nl][8][k] * w2;
    }
    g_mixv[idx]          = make_float4(acc[0], acc[1], acc[2], acc[3]);
    g_mixv[NC + idx]     = make_float4(acc[4], acc[5], acc[6], acc[7]);
    g_mixv[2 * NC + idx] = make_float4(acc[8], 0.f, 0.f, 0.f);
}

// ================= CSR build =================
__global__ void k_hist(const int* __restrict__ ei) {
    int e = blockIdx.x * 256 + threadIdx.x;
    if (e < EE) atomicAdd(&g_cnt[__ldg(ei + e)], 1);
}

__global__ void k_scan() {
    int t = threadIdx.x;
    int base = t * 10;
    int loc[10];
    int s = 0;
#pragma unroll
    for (int i = 0; i < 10; i++) {
        int nn = base + i;
        int v = (nn < NN) ? g_cnt[nn] : 0;
        loc[i] = s; s += v;
    }
    __shared__ int smv[1024];
    smv[t] = s;
    __syncthreads();
    for (int off = 1; off < 1024; off <<= 1) {
        int v = (t >= off) ? smv[t - off] : 0;
        __syncthreads();
        smv[t] += v;
        __syncthreads();
    }
    int pre = (t > 0) ? smv[t - 1] : 0;
#pragma unroll
    for (int i = 0; i < 10; i++) {
        int nn = base + i;
        if (nn < NN) { int o = pre + loc[i]; g_off[nn] = o; g_cnt[nn] = o; }
    }
    if (t == 1023) g_off[NN] = smv[1023];
}

__global__ void k_fill(const int* __restrict__ ei) {
    int e = blockIdx.x * 256 + threadIdx.x;
    if (e < EE) {
        int src = __ldg(ei + e);
        int dst = __ldg(ei + EE + e);
        int pos = atomicAdd(&g_cnt[src], 1);
        g_el[pos] = make_int2(e, dst);
    }
}

// ================= Kernel B: fused edge MLP, 256 threads, output-split ==========
// smem float offsets
#define SW2 0          // 64*128  = 8192
#define SW3 8192       // 128*192 = 24576  -> ends 32768
#define SH2 32768      // 128 x 128 = 16384 -> ends 49152 (W1 overlays start, dead after L1)
#define SW1 32768      // 32*64 = 2048
#define SH1 49152      // 64 x 128 = 8192  -> ends 57344 (ea staging + h1)
#define SBUF 49152     // overlay of SH1 after layer2: [128][66] = 8448 -> ends 57600
#define SMEM_FLOATS 57600

__global__ void __launch_bounds__(256, 1) k_mlp(
    const float* __restrict__ ea, const float* __restrict__ ew,
    const float* __restrict__ W1, const float* __restrict__ b1,
    const float* __restrict__ W2, const float* __restrict__ b2,
    const float* __restrict__ W3, const float* __restrict__ b3)
{
    extern __shared__ float sm[];
    int tid = threadIdx.x;
    int eh = tid & 127;       // edge within block
    int half = tid >> 7;      // output half

    // ---- cooperative staging ----
    {
        float4* d; const float4* s;
        d = (float4*)(sm + SW2); s = (const float4*)W2;
        for (int i = tid; i < 2048; i += 256) d[i] = s[i];
        d = (float4*)(sm + SW3); s = (const float4*)W3;
        for (int i = tid; i < 6144; i += 256) d[i] = s[i];
        d = (float4*)(sm + SW1); s = (const float4*)W1;
        for (int i = tid; i < 512; i += 256) d[i] = s[i];
        // edge_attr [128 edges][32] -> sm[SH1 + r*128 + e_local]
        const float4* g = (const float4*)(ea + (size_t)blockIdx.x * 128 * 32);
        for (int i = tid; i < 1024; i += 256) {
            float4 v = g[i];
            int el = i >> 3, r0 = (i & 7) * 4;
            sm[SH1 + (r0 + 0) * 128 + el] = v.x;
            sm[SH1 + (r0 + 1) * 128 + el] = v.y;
            sm[SH1 + (r0 + 2) * 128 + el] = v.z;
            sm[SH1 + (r0 + 3) * 128 + el] = v.w;
        }
    }
    __syncthreads();

    // ---- layer 1: 32 -> 64, this thread computes outputs [half*32, half*32+32) ----
    unsigned long long acc2[32];
    {
        const float* bp = b1 + half * 32;
#pragma unroll
        for (int j = 0; j < 16; j++) {
            unsigned lo = __float_as_uint(__ldg(bp + 2 * j));
            unsigned hi = __float_as_uint(__ldg(bp + 2 * j + 1));
            PACK2(acc2[j], lo, hi);
        }
        for (int r = 0; r < 32; r++) {
            float x = sm[SH1 + r * 128 + eh];
            unsigned long long xx; unsigned xb = __float_as_uint(x);
            PACK2(xx, xb, xb);
            const ulonglong2* wr = (const ulonglong2*)(sm + SW1 + r * 64 + half * 32);
#pragma unroll
            for (int q = 0; q < 8; q++) {
                ulonglong2 w = wr[q];
                FMA2(acc2[2 * q],     xx, w.x, acc2[2 * q]);
                FMA2(acc2[2 * q + 1], xx, w.y, acc2[2 * q + 1]);
            }
        }
    }
    __syncthreads();   // all ea reads done before h1 overwrites SH1
#pragma unroll
    for (int j = 0; j < 16; j++) {
        unsigned lo, hi; UNPACK2(lo, hi, acc2[j]);
        sm[SH1 + (half * 32 + 2 * j)     * 128 + eh] = silu_f(__uint_as_float(lo));
        sm[SH1 + (half * 32 + 2 * j + 1) * 128 + eh] = silu_f(__uint_as_float(hi));
    }
    __syncthreads();   // h1 complete; also all W1 reads done before h2 clobbers SW1 region

    // ---- layer 2: 64 -> 128, outputs [half*64, half*64+64) ----
    {
        const float* bp = b2 + half * 64;
#pragma unroll
        for (int j = 0; j < 32; j++) {
            unsigned lo = __float_as_uint(__ldg(bp + 2 * j));
            unsigned hi = __float_as_uint(__ldg(bp + 2 * j + 1));
            PACK2(acc2[j], lo, hi);
        }
        for (int k = 0; k < 64; k++) {
            float x = sm[SH1 + k * 128 + eh];
            unsigned long long xx; unsigned xb = __float_as_uint(x);
            PACK2(xx, xb, xb);
            const ulonglong2* wr = (const ulonglong2*)(sm + SW2 + k * 128 + half * 64);
#pragma unroll
            for (int q = 0; q < 16; q++) {
                ulonglong2 w = wr[q];
                FMA2(acc2[2 * q],     xx, w.x, acc2[2 * q]);
                FMA2(acc2[2 * q + 1], xx, w.y, acc2[2 * q + 1]);
            }
        }
    }
    // h2 goes to SH2 (overlays dead W1 region); layer-2 reads SH1 only. Safe.
#pragma unroll
    for (int j = 0; j < 32; j++) {
        unsigned lo, hi; UNPACK2(lo, hi, acc2[j]);
        sm[SH2 + (half * 64 + 2 * j)     * 128 + eh] = silu_f(__uint_as_float(lo));
        sm[SH2 + (half * 64 + 2 * j + 1) * 128 + eh] = silu_f(__uint_as_float(hi));
    }
    __syncthreads();   // h2 complete; SH1 now dead -> reusable as SBUF

    // ---- cutoff ----
    int e_glob = blockIdx.x * 128 + eh;
    float wgt = __ldg(ew + e_glob);
    float cw = (wgt < CUT) ? 0.5f * (cosf(wgt * (float)(M_PI / 5.0)) + 1.0f) : 0.0f;

    // ---- layer 3: 128 -> 192, 3 chunks; outputs [oc*64 + half*32, +32) ----
#pragma unroll 1
    for (int oc = 0; oc < 3; oc++) {
        const float* bp = b3 + oc * 64 + half * 32;
#pragma unroll
        for (int j = 0; j < 16; j++) {
            unsigned lo = __float_as_uint(__ldg(bp + 2 * j));
            unsigned hi = __float_as_uint(__ldg(bp + 2 * j + 1));
            PACK2(acc2[j], lo, hi);
        }
        for (int k = 0; k < 128; k++) {
            float x = sm[SH2 + k * 128 + eh];
            unsigned long long xx; unsigned xb = __float_as_uint(x);
            PACK2(xx, xb, xb);
            const ulonglong2* wr = (const ulonglong2*)(sm + SW3 + k * 192 + oc * 64 + half * 32);
#pragma unroll
            for (int q = 0; q < 8; q++) {
                ulonglong2 w = wr[q];
                FMA2(acc2[2 * q],     xx, w.x, acc2[2 * q]);
                FMA2(acc2[2 * q + 1], xx, w.y, acc2[2 * q + 1]);
            }
        }
        // silu * cw -> sbuf[eh][half*32 + j]  (stride 66 rows)
#pragma unroll
        for (int j = 0; j < 16; j++) {
            unsigned lo, hi; UNPACK2(lo, hi, acc2[j]);
            sm[SBUF + eh * 66 + half * 32 + 2 * j]     = silu_f(__uint_as_float(lo)) * cw;
            sm[SBUF + eh * 66 + half * 32 + 2 * j + 1] = silu_f(__uint_as_float(hi)) * cw;
        }
        __syncthreads();
        // coalesced store: lanes sweep columns
        for (int i = tid; i < 8192; i += 256) {
            int el2 = i >> 6, c = i & 63;
            g_af[(size_t)(blockIdx.x * 128 + el2) * 192 + oc * 64 + c] = sm[SBUF + el2 * 66 + c];
        }
        __syncthreads();
    }
}

// ================= Kernel C: CSR gather + accumulate, 4 edge-slices =============
__global__ void k_msg(void) {
    int n = blockIdx.x;
    int tid = threadIdx.x;
    int s = tid >> 6, c = tid & 63;
    __shared__ float red[3][64][13];

    int i0 = g_off[n], i1 = g_off[n + 1];
    float a0v0 = 0.f, a0v1 = 0.f, a0v2 = 0.f, a0v3 = 0.f;
    float a1v0 = 0.f, a1v1 = 0.f, a1v2 = 0.f, a1v3 = 0.f;
    float a2v = 0.f;
    for (int i = i0 + s; i < i1; i += 4) {
        int2 cur = __ldg(&g_el[i]);
        const float* ap = g_af + (size_t)cur.x * 192 + c * 3;
        float a0 = __ldg(ap), a1 = __ldg(ap + 1), a2 = __ldg(ap + 2);
        int mi = cur.y * CC + c;
        float4 m0 = __ldg(&g_mixv[mi]);
        float4 m1 = __ldg(&g_mixv[NC + mi]);
        float4 m2 = __ldg(&g_mixv[2 * NC + mi]);
        a0v0 += a0 * m0.x; a0v1 += a1 * m0.y; a0v2 += a1 * m0.z; a0v3 += a1 * m0.w;
        a1v0 += a2 * m1.x; a1v1 += a2 * m1.y; a1v2 += a2 * m1.z; a1v3 += a2 * m1.w;
        a2v  += a2 * m2.x;
    }
    if (s > 0) {
        float* rp = red[s - 1][c];
        rp[0] = a0v0; rp[1] = a0v1; rp[2] = a0v2; rp[3] = a0v3;
        rp[4] = a1v0; rp[5] = a1v1; rp[6] = a1v2; rp[7] = a1v3;
        rp[8] = a2v;
    }
    __syncthreads();
    if (s == 0) {
#pragma unroll
        for (int ss = 0; ss < 3; ss++) {
            float* rp = red[ss][c];
            a0v0 += rp[0]; a0v1 += rp[1]; a0v2 += rp[2]; a0v3 += rp[3];
            a1v0 += rp[4]; a1v1 += rp[5]; a1v2 += rp[6]; a1v3 += rp[7];
            a2v  += rp[8];
        }
        int idx = n * CC + c;
        g_msgv[idx]          = make_float4(a0v0, a0v1, a0v2, a0v3);
        g_msgv[NC + idx]     = make_float4(a1v0, a1v1, a1v2, a1v3);
        g_msgv[2 * NC + idx] = make_float4(a2v, 0.f, 0.f, 0.f);
    }
}

// ================= Kernel D: combine, second decomposition+mix, output ==================
__global__ void k_out(const float* __restrict__ Wt, float* __restrict__ out) {
    int tid = threadIdx.x;
    int nl = tid >> 6, c = tid & 63;
    int n = blockIdx.x * 4 + nl;
    __shared__ float sp[4][9][CC];

    int idx = n * CC + c;
    float4 g0 = g_msgv[idx], g1 = g_msgv[NC + idx], g2 = g_msgv[2 * NC + idx];
    float4 y0 = g_mixv[idx], y1 = g_mixv[NC + idx], y2 = g_mixv[2 * NC + idx];
    float m9[9] = { g0.x, g0.y, g0.z, g0.w, g1.x, g1.y, g1.z, g1.w, g2.x };
    float y9[9] = { y0.x, y0.y, y0.z, y0.w, y1.x, y1.y, y1.z, y1.w, y2.x };

    float Mg[3][3] = {
        { m9[0]+m9[4],  m9[1]+m9[6],  m9[2]+m9[7] },
        { m9[6]-m9[1],  m9[0]+m9[5],  m9[3]+m9[8] },
        { m9[7]-m9[2],  m9[8]-m9[3],  m9[0]-m9[4]-m9[5] }
    };
    float Yf[3][3] = {
        { y9[0]+y9[4],  y9[1]+y9[6],  y9[2]+y9[7] },
        { y9[6]-y9[1],  y9[0]+y9[5],  y9[3]+y9[8] },
        { y9[7]-y9[2],  y9[8]-y9[3],  y9[0]-y9[4]-y9[5] }
    };

    float M[3][3];
#pragma unroll
    for (int i = 0; i < 3; i++)
#pragma unroll
        for (int j = 0; j < 3; j++) {
            float sacc = 0.f;
#pragma unroll
            for (int k = 0; k < 3; k++)
                sacc += Mg[i][k] * Yf[k][j] + Yf[i][k] * Mg[k][j];
            M[i][j] = sacc;
        }

    float tn = 0.f;
#pragma unroll
    for (int i = 0; i < 3; i++)
#pragma unroll
        for (int j = 0; j < 3; j++) tn += M[i][j] * M[i][j];
    float inv = 1.0f / (tn + 1.0f);

    float i0 = (M[0][0] + M[1][1] + M[2][2]) * (1.0f / 3.0f);
    sp[nl][0][c] = i0 * inv;
    sp[nl][1][c] = 0.5f * (M[0][1] - M[1][0]) * inv;
    sp[nl][2][c] = 0.5f * (M[0][2] - M[2][0]) * inv;
    sp[nl][3][c] = 0.5f * (M[1][2] - M[2][1]) * inv;
    sp[nl][4][c] = (M[0][0] - i0) * inv;
    sp[nl][5][c] = (M[1][1] - i0) * inv;
    sp[nl][6][c] = 0.5f * (M[0][1] + M[1][0]) * inv;
    sp[nl][7][c] = 0.5f * (M[0][2] + M[2][0]) * inv;
    sp[nl][8][c] = 0.5f * (M[1][2] + M[2][1]) * inv;
    __syncthreads();

    float acc[9];
#pragma unroll
    for (int j = 0; j < 9; j++) acc[j] = 0.f;
    for (int k = 0; k < CC; k++) {
        float w3 = __ldg(Wt + 3*4096 + k * CC + c);
        float w4 = __ldg(Wt + 4*4096 + k * CC + c);
        float w5 = __ldg(Wt + 5*4096 + k * CC + c);
        acc[0] += sp[nl][0][k] * w3;
        acc[1] += sp[nl][1][k] * w4;
        acc[2] += sp[nl][2][k] * w4;
        acc[3] += sp[nl][3][k] * w4;
        acc[4] += sp[nl][4][k] * w5;
        acc[5] += sp[nl][5][k] * w5;
        acc[6] += sp[nl][6][k] * w5;
        acc[7] += sp[nl][7][k] * w5;
        acc[8] += sp[nl][8][k] * w5;
    }

    float D[3][3] = {
        { acc[0]+acc[4],  acc[1]+acc[6],  acc[2]+acc[7] },
        { acc[6]-acc[1],  acc[0]+acc[5],  acc[3]+acc[8] },
        { acc[7]-acc[2],  acc[8]-acc[3],  acc[0]-acc[4]-acc[5] }
    };
    float D2[3][3];
#pragma unroll
    for (int i = 0; i < 3; i++)
#pragma unroll
        for (int j = 0; j < 3; j++) {
            float sacc = 0.f;
#pragma unroll
            for (int k = 0; k < 3; k++) sacc += D[i][k] * D[k][j];
            D2[i][j] = sacc;
        }

    const float* xnp = g_Xn + (size_t)idx * 9;
    float* op = out + (size_t)idx * 9;
#pragma unroll
    for (int i = 0; i < 3; i++)
#pragma unroll
        for (int j = 0; j < 3; j++)
            op[3*i+j] = xnp[3*i+j] + D[i][j] + D2[i][j];
}

// ======================= launch =======================
extern "C" void kernel_launch(void* const* d_in, const int* in_sizes, int n_in,
                              void* d_out, int out_size) {
    const float* X  = (const float*)d_in[0];
    const int*   ei = (const int*)  d_in[1];
    const float* ew = (const float*)d_in[2];
    const float* ea = (const float*)d_in[3];
    const float* W1 = (const float*)d_in[4];
    const float* b1 = (const float*)d_in[5];
    const float* W2 = (const float*)d_in[6];
    const float* b2 = (const float*)d_in[7];
    const float* W3 = (const float*)d_in[8];
    const float* b3 = (const float*)d_in[9];
    const float* Wt = (const float*)d_in[10];

    const int smem_bytes = SMEM_FLOATS * 4;   // 230400
    cudaFuncSetAttribute(k_mlp, cudaFuncAttributeMaxDynamicSharedMemorySize, smem_bytes);

    k_node<<<NN / 4, 256>>>(X, Wt);
    k_hist<<<(EE + 255) / 256, 256>>>(ei);
    k_scan<<<1, 1024>>>();
    k_mlp<<<EE / 128, 256, smem_bytes>>>(ea, ew, W1, b1, W2, b2, W3, b3);   // 4th launch -> profiled
    k_fill<<<(EE + 255) / 256, 256>>>(ei);
    k_msg<<<NN, 256>>>();
    k_out<<<NN / 4, 256>>>(Wt, (float*)d_out);
}

// round 10
// speedup vs baseline: 2.0444x; 1.2151x over previous
#include <cuda_runtime.h>
#include <math.h>
#include <stdint.h>

#define NN 10000
#define EE 160000
#define CC 64
#define RR 32
#define CUT 5.0f
#define NC (NN * CC)

// ---------------- device scratch ----------------
__device__ float  g_Xn [NN * CC * 9];
__device__ float4 g_mixv[3 * NC];
__device__ float4 g_msgv[3 * NC];
__device__ float  g_af [(size_t)EE * 192];
__device__ int  g_cnt[NN];
__device__ int  g_off[NN + 1];
__device__ int2 g_el [EE];

__device__ __forceinline__ float silu_f(float x) { return x / (1.0f + __expf(-x)); }

// packed f32x2 helpers
#define FMA2(d, a, b, c) asm("fma.rn.f32x2 %0, %1, %2, %3;" : "=l"(d) : "l"(a), "l"(b), "l"(c))
#define PACK2(d, lo, hi) asm("mov.b64 %0, {%1, %2};" : "=l"(d) : "r"(lo), "r"(hi))
#define UNPACK2(lo, hi, v) asm("mov.b64 {%0, %1}, %2;" : "=r"(lo), "=r"(hi) : "l"(v))

// ================= Kernel A: node prep + decompose + channel-mix (4 nodes/block) ======
__global__ void k_node(const float* __restrict__ X, const float* __restrict__ Wt) {
    int tid = threadIdx.x;
    int nl = tid >> 6, c = tid & 63;
    int n = blockIdx.x * 4 + nl;
    __shared__ float sp[4][9][CC];

    if (tid < 4) g_cnt[blockIdx.x * 4 + tid] = 0;

    int idx = n * CC + c;
    const float* xp = X + (size_t)idx * 9;
    float t[9];
#pragma unroll
    for (int j = 0; j < 9; j++) t[j] = xp[j];
    float n2 = 0.f;
#pragma unroll
    for (int j = 0; j < 9; j++) n2 += t[j] * t[j];
    float inv = 1.0f / (n2 + 1.0f);

    float xn[9];
    float* xnp = g_Xn + (size_t)idx * 9;
#pragma unroll
    for (int j = 0; j < 9; j++) { xn[j] = t[j] * inv; xnp[j] = xn[j]; }

    float i0 = (xn[0] + xn[4] + xn[8]) * (1.0f / 3.0f);
    sp[nl][0][c] = i0;
    sp[nl][1][c] = 0.5f * (xn[1] - xn[3]);
    sp[nl][2][c] = 0.5f * (xn[2] - xn[6]);
    sp[nl][3][c] = 0.5f * (xn[5] - xn[7]);
    sp[nl][4][c] = xn[0] - i0;
    sp[nl][5][c] = xn[4] - i0;
    sp[nl][6][c] = 0.5f * (xn[1] + xn[3]);
    sp[nl][7][c] = 0.5f * (xn[2] + xn[6]);
    sp[nl][8][c] = 0.5f * (xn[5] + xn[7]);
    __syncthreads();

    float acc[9];
#pragma unroll
    for (int j = 0; j < 9; j++) acc[j] = 0.f;
    for (int k = 0; k < CC; k++) {
        float w0 = __ldg(Wt +        k * CC + c);
        float w1 = __ldg(Wt + 4096 + k * CC + c);
        float w2 = __ldg(Wt + 8192 + k * CC + c);
        acc[0] += sp[nl][0][k] * w0;
        acc[1] += sp[nl][1][k] * w1;
        acc[2] += sp[nl][2][k] * w1;
        acc[3] += sp[nl][3][k] * w1;
        acc[4] += sp[nl][4][k] * w2;
        acc[5] += sp[nl][5][k] * w2;
        acc[6] += sp[nl][6][k] * w2;
        acc[7] += sp[nl][7][k] * w2;
        acc[8] += sp[nl][8][k] * w2;
    }
    g_mixv[idx]          = make_float4(acc[0], acc[1], acc[2], acc[3]);
    g_mixv[NC + idx]     = make_float4(acc[4], acc[5], acc[6], acc[7]);
    g_mixv[2 * NC + idx] = make_float4(acc[8], 0.f, 0.f, 0.f);
}

// ================= CSR build =================
__global__ void k_hist(const int* __restrict__ ei) {
    int e = blockIdx.x * 256 + threadIdx.x;
    if (e < EE) atomicAdd(&g_cnt[__ldg(ei + e)], 1);
}

__global__ void k_scan() {
    int t = threadIdx.x;
    int base = t * 10;
    int loc[10];
    int s = 0;
#pragma unroll
    for (int i = 0; i < 10; i++) {
        int nn = base + i;
        int v = (nn < NN) ? g_cnt[nn] : 0;
        loc[i] = s; s += v;
    }
    __shared__ int smv[1024];
    smv[t] = s;
    __syncthreads();
    for (int off = 1; off < 1024; off <<= 1) {
        int v = (t >= off) ? smv[t - off] : 0;
        __syncthreads();
        smv[t] += v;
        __syncthreads();
    }
    int pre = (t > 0) ? smv[t - 1] : 0;
#pragma unroll
    for (int i = 0; i < 10; i++) {
        int nn = base + i;
        if (nn < NN) { int o = pre + loc[i]; g_off[nn] = o; g_cnt[nn] = o; }
    }
    if (t == 1023) g_off[NN] = smv[1023];
}

__global__ void k_fill(const int* __restrict__ ei) {
    int e = blockIdx.x * 256 + threadIdx.x;
    if (e < EE) {
        int src = __ldg(ei + e);
        int dst = __ldg(ei + EE + e);
        int pos = atomicAdd(&g_cnt[src], 1);
        g_el[pos] = make_int2(e, dst);
    }
}

// ================= Kernel B: fused edge MLP, 256 threads, edge-pair blocking ==========
// smem float offsets (identical layout to the passing R7 kernel)
#define SW2 0          // 64*128  = 8192
#define SW3 8192       // 128*192 = 24576  -> ends 32768
#define SH2 32768      // 128 x 128 = 16384 -> ends 49152 (W1 overlays start, dead after L1)
#define SW1 32768      // 32*64 = 2048
#define SH1 49152      // 64 x 128 = 8192  -> ends 57344 (ea staging + h1)
#define SBUF 49152     // overlay of SH1 after layer2: [128][66] = 8448 -> ends 57600
#define SMEM_FLOATS 57600

__global__ void __launch_bounds__(256, 1) k_mlp(
    const float* __restrict__ ea, const float* __restrict__ ew,
    const float* __restrict__ W1, const float* __restrict__ b1,
    const float* __restrict__ W2, const float* __restrict__ b2,
    const float* __restrict__ W3, const float* __restrict__ b3)
{
    extern __shared__ float sm[];
    int tid = threadIdx.x;
    int ep = tid & 63;        // edge pair -> edges e0 = 2*ep, e0+1
    int sl = tid >> 6;        // output slice 0..3
    int e0 = 2 * ep;

    // ---- cooperative staging ----
    {
        float4* d; const float4* s;
        d = (float4*)(sm + SW2); s = (const float4*)W2;
        for (int i = tid; i < 2048; i += 256) d[i] = s[i];
        d = (float4*)(sm + SW3); s = (const float4*)W3;
        for (int i = tid; i < 6144; i += 256) d[i] = s[i];
        d = (float4*)(sm + SW1); s = (const float4*)W1;
        for (int i = tid; i < 512; i += 256) d[i] = s[i];
        // edge_attr [128 edges][32] -> sm[SH1 + r*128 + e_local]
        const float4* g = (const float4*)(ea + (size_t)blockIdx.x * 128 * 32);
        for (int i = tid; i < 1024; i += 256) {
            float4 v = g[i];
            int el = i >> 3, r0 = (i & 7) * 4;
            sm[SH1 + (r0 + 0) * 128 + el] = v.x;
            sm[SH1 + (r0 + 1) * 128 + el] = v.y;
            sm[SH1 + (r0 + 2) * 128 + el] = v.z;
            sm[SH1 + (r0 + 3) * 128 + el] = v.w;
        }
    }
    __syncthreads();

    unsigned long long acc2[32];   // up to 32 packed pairs (layer 2)

    // ---- layer 1: 32 -> 64; outputs [sl*16, sl*16+16) for edges e0, e0+1 ----
    {
        const float* bp = b1 + sl * 16;
#pragma unroll
        for (int j = 0; j < 8; j++) {
            unsigned lo = __float_as_uint(__ldg(bp + 2 * j));
            unsigned hi = __float_as_uint(__ldg(bp + 2 * j + 1));
            PACK2(acc2[j], lo, hi);
            acc2[8 + j] = acc2[j];
        }
        for (int r = 0; r < 32; r++) {
            float2 xv = *(float2*)(sm + SH1 + r * 128 + e0);
            unsigned long long x0, x1;
            unsigned xa = __float_as_uint(xv.x), xb = __float_as_uint(xv.y);
            PACK2(x0, xa, xa); PACK2(x1, xb, xb);
            const ulonglong2* wr = (const ulonglong2*)(sm + SW1 + r * 64 + sl * 16);
#pragma unroll
            for (int q = 0; q < 4; q++) {
                ulonglong2 w = wr[q];
                FMA2(acc2[2 * q],         x0, w.x, acc2[2 * q]);
                FMA2(acc2[2 * q + 1],     x0, w.y, acc2[2 * q + 1]);
                FMA2(acc2[8 + 2 * q],     x1, w.x, acc2[8 + 2 * q]);
                FMA2(acc2[8 + 2 * q + 1], x1, w.y, acc2[8 + 2 * q + 1]);
            }
        }
    }
    __syncthreads();   // all ea reads done before h1 overwrites SH1
#pragma unroll
    for (int j = 0; j < 8; j++) {
        unsigned l0, h0, l1, h1;
        UNPACK2(l0, h0, acc2[j]);
        UNPACK2(l1, h1, acc2[8 + j]);
        *(float2*)(sm + SH1 + (sl * 16 + 2 * j)     * 128 + e0) =
            make_float2(silu_f(__uint_as_float(l0)), silu_f(__uint_as_float(l1)));
        *(float2*)(sm + SH1 + (sl * 16 + 2 * j + 1) * 128 + e0) =
            make_float2(silu_f(__uint_as_float(h0)), silu_f(__uint_as_float(h1)));
    }
    __syncthreads();   // h1 complete; W1 reads done before h2 clobbers SW1 region

    // ---- layer 2: 64 -> 128; outputs [sl*32, sl*32+32) for both edges ----
    {
        const float* bp = b2 + sl * 32;
#pragma unroll
        for (int j = 0; j < 16; j++) {
            unsigned lo = __float_as_uint(__ldg(bp + 2 * j));
            unsigned hi = __float_as_uint(__ldg(bp + 2 * j + 1));
            PACK2(acc2[j], lo, hi);
            acc2[16 + j] = acc2[j];
        }
        for (int k = 0; k < 64; k++) {
            float2 xv = *(float2*)(sm + SH1 + k * 128 + e0);
            unsigned long long x0, x1;
            unsigned xa = __float_as_uint(xv.x), xb = __float_as_uint(xv.y);
            PACK2(x0, xa, xa); PACK2(x1, xb, xb);
            const ulonglong2* wr = (const ulonglong2*)(sm + SW2 + k * 128 + sl * 32);
#pragma unroll
            for (int q = 0; q < 8; q++) {
                ulonglong2 w = wr[q];
                FMA2(acc2[2 * q],          x0, w.x, acc2[2 * q]);
                FMA2(acc2[2 * q + 1],      x0, w.y, acc2[2 * q + 1]);
                FMA2(acc2[16 + 2 * q],     x1, w.x, acc2[16 + 2 * q]);
                FMA2(acc2[16 + 2 * q + 1], x1, w.y, acc2[16 + 2 * q + 1]);
            }
        }
    }
    // h2 -> SH2 (overlays dead W1); layer-2 readers touch SH1/SW2 only. Safe without barrier here.
#pragma unroll
    for (int j = 0; j < 16; j++) {
        unsigned l0, h0, l1, h1;
        UNPACK2(l0, h0, acc2[j]);
        UNPACK2(l1, h1, acc2[16 + j]);
        *(float2*)(sm + SH2 + (sl * 32 + 2 * j)     * 128 + e0) =
            make_float2(silu_f(__uint_as_float(l0)), silu_f(__uint_as_float(l1)));
        *(float2*)(sm + SH2 + (sl * 32 + 2 * j + 1) * 128 + e0) =
            make_float2(silu_f(__uint_as_float(h0)), silu_f(__uint_as_float(h1)));
    }
    __syncthreads();   // h2 complete; SH1 dead -> SBUF usable

    // ---- cutoff (per edge) ----
    int eg0 = blockIdx.x * 128 + e0;
    float w0 = __ldg(ew + eg0);
    float w1 = __ldg(ew + eg0 + 1);
    float cw0 = (w0 < CUT) ? 0.5f * (cosf(w0 * (float)(M_PI / 5.0)) + 1.0f) : 0.0f;
    float cw1 = (w1 < CUT) ? 0.5f * (cosf(w1 * (float)(M_PI / 5.0)) + 1.0f) : 0.0f;

    // ---- layer 3: 128 -> 192, 3 chunks; outputs [oc*64 + sl*16, +16) for both edges ----
#pragma unroll 1
    for (int oc = 0; oc < 3; oc++) {
        const float* bp = b3 + oc * 64 + sl * 16;
#pragma unroll
        for (int j = 0; j < 8; j++) {
            unsigned lo = __float_as_uint(__ldg(bp + 2 * j));
            unsigned hi = __float_as_uint(__ldg(bp + 2 * j + 1));
            PACK2(acc2[j], lo, hi);
            acc2[8 + j] = acc2[j];
        }
        for (int k = 0; k < 128; k++) {
            float2 xv = *(float2*)(sm + SH2 + k * 128 + e0);
            unsigned long long x0, x1;
            unsigned xa = __float_as_uint(xv.x), xb = __float_as_uint(xv.y);
            PACK2(x0, xa, xa); PACK2(x1, xb, xb);
            const ulonglong2* wr = (const ulonglong2*)(sm + SW3 + k * 192 + oc * 64 + sl * 16);
#pragma unroll
            for (int q = 0; q < 4; q++) {
                ulonglong2 w = wr[q];
                FMA2(acc2[2 * q],         x0, w.x, acc2[2 * q]);
                FMA2(acc2[2 * q + 1],     x0, w.y, acc2[2 * q + 1]);
                FMA2(acc2[8 + 2 * q],     x1, w.x, acc2[8 + 2 * q]);
                FMA2(acc2[8 + 2 * q + 1], x1, w.y, acc2[8 + 2 * q + 1]);
            }
        }
        // silu * cw -> sbuf[e][o] (row stride 66)
#pragma unroll
        for (int j = 0; j < 8; j++) {
            unsigned l0, h0, l1, h1;
            UNPACK2(l0, h0, acc2[j]);
            UNPACK2(l1, h1, acc2[8 + j]);
            int ob = sl * 16 + 2 * j;
            sm[SBUF + e0 * 66 + ob]           = silu_f(__uint_as_float(l0)) * cw0;
            sm[SBUF + e0 * 66 + ob + 1]       = silu_f(__uint_as_float(h0)) * cw0;
            sm[SBUF + (e0 + 1) * 66 + ob]     = silu_f(__uint_as_float(l1)) * cw1;
            sm[SBUF + (e0 + 1) * 66 + ob + 1] = silu_f(__uint_as_float(h1)) * cw1;
        }
        __syncthreads();
        // coalesced store: float2 sweep of columns
        for (int i = tid; i < 4096; i += 256) {
            int el2 = i >> 5, c2 = (i & 31) * 2;
            float2 v = *(float2*)(sm + SBUF + el2 * 66 + c2);
            *(float2*)(g_af + (size_t)(blockIdx.x * 128 + el2) * 192 + oc * 64 + c2) = v;
        }
        __syncthreads();
    }
}

// ================= Kernel C: CSR gather + accumulate, 4 edge-slices =============
__global__ void k_msg(void) {
    int n = blockIdx.x;
    int tid = threadIdx.x;
    int s = tid >> 6, c = tid & 63;
    __shared__ float red[3][64][13];

    int i0 = g_off[n], i1 = g_off[n + 1];
    float a0v0 = 0.f, a0v1 = 0.f, a0v2 = 0.f, a0v3 = 0.f;
    float a1v0 = 0.f, a1v1 = 0.f, a1v2 = 0.f, a1v3 = 0.f;
    float a2v = 0.f;
    for (int i = i0 + s; i < i1; i += 4) {
        int2 cur = __ldg(&g_el[i]);
        const float* ap = g_af + (size_t)cur.x * 192 + c * 3;
        float a0 = __ldg(ap), a1 = __ldg(ap + 1), a2 = __ldg(ap + 2);
        int mi = cur.y * CC + c;
        float4 m0 = __ldg(&g_mixv[mi]);
        float4 m1 = __ldg(&g_mixv[NC + mi]);
        float4 m2 = __ldg(&g_mixv[2 * NC + mi]);
        a0v0 += a0 * m0.x; a0v1 += a1 * m0.y; a0v2 += a1 * m0.z; a0v3 += a1 * m0.w;
        a1v0 += a2 * m1.x; a1v1 += a2 * m1.y; a1v2 += a2 * m1.z; a1v3 += a2 * m1.w;
        a2v  += a2 * m2.x;
    }
    if (s > 0) {
        float* rp = red[s - 1][c];
        rp[0] = a0v0; rp[1] = a0v1; rp[2] = a0v2; rp[3] = a0v3;
        rp[4] = a1v0; rp[5] = a1v1; rp[6] = a1v2; rp[7] = a1v3;
        rp[8] = a2v;
    }
    __syncthreads();
    if (s == 0) {
#pragma unroll
        for (int ss = 0; ss < 3; ss++) {
            float* rp = red[ss][c];
            a0v0 += rp[0]; a0v1 += rp[1]; a0v2 += rp[2]; a0v3 += rp[3];
            a1v0 += rp[4]; a1v1 += rp[5]; a1v2 += rp[6]; a1v3 += rp[7];
            a2v  += rp[8];
        }
        int idx = n * CC + c;
        g_msgv[idx]          = make_float4(a0v0, a0v1, a0v2, a0v3);
        g_msgv[NC + idx]     = make_float4(a1v0, a1v1, a1v2, a1v3);
        g_msgv[2 * NC + idx] = make_float4(a2v, 0.f, 0.f, 0.f);
    }
}

// ================= Kernel D: combine, second decomposition+mix, output ==================
__global__ void k_out(const float* __restrict__ Wt, float* __restrict__ out) {
    int tid = threadIdx.x;
    int nl = tid >> 6, c = tid & 63;
    int n = blockIdx.x * 4 + nl;
    __shared__ float sp[4][9][CC];

    int idx = n * CC + c;
    float4 g0 = g_msgv[idx], g1 = g_msgv[NC + idx], g2 = g_msgv[2 * NC + idx];
    float4 y0 = g_mixv[idx], y1 = g_mixv[NC + idx], y2 = g_mixv[2 * NC + idx];
    float m9[9] = { g0.x, g0.y, g0.z, g0.w, g1.x, g1.y, g1.z, g1.w, g2.x };
    float y9[9] = { y0.x, y0.y, y0.z, y0.w, y1.x, y1.y, y1.z, y1.w, y2.x };

    float Mg[3][3] = {
        { m9[0]+m9[4],  m9[1]+m9[6],  m9[2]+m9[7] },
        { m9[6]-m9[1],  m9[0]+m9[5],  m9[3]+m9[8] },
        { m9[7]-m9[2],  m9[8]-m9[3],  m9[0]-m9[4]-m9[5] }
    };
    float Yf[3][3] = {
        { y9[0]+y9[4],  y9[1]+y9[6],  y9[2]+y9[7] },
        { y9[6]-y9[1],  y9[0]+y9[5],  y9[3]+y9[8] },
        { y9[7]-y9[2],  y9[8]-y9[3],  y9[0]-y9[4]-y9[5] }
    };

    float M[3][3];
#pragma unroll
    for (int i = 0; i < 3; i++)
#pragma unroll
        for (int j = 0; j < 3; j++) {
            float sacc = 0.f;
#pragma unroll
            for (int k = 0; k < 3; k++)
                sacc += Mg[i][k] * Yf[k][j] + Yf[i][k] * Mg[k][j];
            M[i][j] = sacc;
        }

    float tn = 0.f;
#pragma unroll
    for (int i = 0; i < 3; i++)
#pragma unroll
        for (int j = 0; j < 3; j++) tn += M[i][j] * M[i][j];
    float inv = 1.0f / (tn + 1.0f);

    float i0 = (M[0][0] + M[1][1] + M[2][2]) * (1.0f / 3.0f);
    sp[nl][0][c] = i0 * inv;
    sp[nl][1][c] = 0.5f * (M[0][1] - M[1][0]) * inv;
    sp[nl][2][c] = 0.5f * (M[0][2] - M[2][0]) * inv;
    sp[nl][3][c] = 0.5f * (M[1][2] - M[2][1]) * inv;
    sp[nl][4][c] = (M[0][0] - i0) * inv;
    sp[nl][5][c] = (M[1][1] - i0) * inv;
    sp[nl][6][c] = 0.5f * (M[0][1] + M[1][0]) * inv;
    sp[nl][7][c] = 0.5f * (M[0][2] + M[2][0]) * inv;
    sp[nl][8][c] = 0.5f * (M[1][2] + M[2][1]) * inv;
    __syncthreads();

    float acc[9];
#pragma unroll
    for (int j = 0; j < 9; j++) acc[j] = 0.f;
    for (int k = 0; k < CC; k++) {
        float w3 = __ldg(Wt + 3*4096 + k * CC + c);
        float w4 = __ldg(Wt + 4*4096 + k * CC + c);
        float w5 = __ldg(Wt + 5*4096 + k * CC + c);
        acc[0] += sp[nl][0][k] * w3;
        acc[1] += sp[nl][1][k] * w4;
        acc[2] += sp[nl][2][k] * w4;
        acc[3] += sp[nl][3][k] * w4;
        acc[4] += sp[nl][4][k] * w5;
        acc[5] += sp[nl][5][k] * w5;
        acc[6] += sp[nl][6][k] * w5;
        acc[7] += sp[nl][7][k] * w5;
        acc[8] += sp[nl][8][k] * w5;
    }

    float D[3][3] = {
        { acc[0]+acc[4],  acc[1]+acc[6],  acc[2]+acc[7] },
        { acc[6]-acc[1],  acc[0]+acc[5],  acc[3]+acc[8] },
        { acc[7]-acc[2],  acc[8]-acc[3],  acc[0]-acc[4]-acc[5] }
    };
    float D2[3][3];
#pragma unroll
    for (int i = 0; i < 3; i++)
#pragma unroll
        for (int j = 0; j < 3; j++) {
            float sacc = 0.f;
#pragma unroll
            for (int k = 0; k < 3; k++) sacc += D[i][k] * D[k][j];
            D2[i][j] = sacc;
        }

    const float* xnp = g_Xn + (size_t)idx * 9;
    float* op = out + (size_t)idx * 9;
#pragma unroll
    for (int i = 0; i < 3; i++)
#pragma unroll
        for (int j = 0; j < 3; j++)
            op[3*i+j] = xnp[3*i+j] + D[i][j] + D2[i][j];
}

// ======================= launch =======================
extern "C" void kernel_launch(void* const* d_in, const int* in_sizes, int n_in,
                              void* d_out, int out_size) {
    const float* X  = (const float*)d_in[0];
    const int*   ei = (const int*)  d_in[1];
    const float* ew = (const float*)d_in[2];
    const float* ea = (const float*)d_in[3];
    const float* W1 = (const float*)d_in[4];
    const float* b1 = (const float*)d_in[5];
    const float* W2 = (const float*)d_in[6];
    const float* b2 = (const float*)d_in[7];
    const float* W3 = (const float*)d_in[8];
    const float* b3 = (const float*)d_in[9];
    const float* Wt = (const float*)d_in[10];

    const int smem_bytes = SMEM_FLOATS * 4;   // 230400
    cudaFuncSetAttribute(k_mlp, cudaFuncAttributeMaxDynamicSharedMemorySize, smem_bytes);

    k_node<<<NN / 4, 256>>>(X, Wt);
    k_hist<<<(EE + 255) / 256, 256>>>(ei);
    k_scan<<<1, 1024>>>();
    k_mlp<<<EE / 128, 256, smem_bytes>>>(ea, ew, W1, b1, W2, b2, W3, b3);   // 4th launch -> profiled
    k_fill<<<(EE + 255) / 256, 256>>>(ei);
    k_msg<<<NN, 256>>>();
    k_out<<<NN / 4, 256>>>(Wt, (float*)d_out);
}

// round 11
// speedup vs baseline: 2.0936x; 1.0241x over previous
#include <cuda_runtime.h>
#include <math.h>
#include <stdint.h>

#define NN 10000
#define EE 160000
#define CC 64
#define RR 32
#define CUT 5.0f
#define NC (NN * CC)

// ---------------- device scratch ----------------
__device__ float  g_Xn [NN * CC * 9];
__device__ float4 g_mixv[3 * NC];
__device__ float4 g_msgv[3 * NC];
__device__ float  g_af [(size_t)EE * 192];
__device__ int  g_cnt[NN];
__device__ int  g_off[NN + 1];
__device__ int2 g_el [EE];

__device__ __forceinline__ float silu_f(float x) { return x / (1.0f + __expf(-x)); }

// packed f32x2 helpers
#define FMA2(d, a, b, c) asm("fma.rn.f32x2 %0, %1, %2, %3;" : "=l"(d) : "l"(a), "l"(b), "l"(c))
#define PACK2(d, lo, hi) asm("mov.b64 %0, {%1, %2};" : "=l"(d) : "r"(lo), "r"(hi))
#define UNPACK2(lo, hi, v) asm("mov.b64 {%0, %1}, %2;" : "=r"(lo), "=r"(hi) : "l"(v))

// ================= Kernel A: node prep + decompose + channel-mix (4 nodes/block) ======
__global__ void k_node(const float* __restrict__ X, const float* __restrict__ Wt) {
    int tid = threadIdx.x;
    int nl = tid >> 6, c = tid & 63;
    int n = blockIdx.x * 4 + nl;
    __shared__ float sp[4][9][CC];

    if (tid < 4) g_cnt[blockIdx.x * 4 + tid] = 0;

    int idx = n * CC + c;
    const float* xp = X + (size_t)idx * 9;
    float t[9];
#pragma unroll
    for (int j = 0; j < 9; j++) t[j] = xp[j];
    float n2 = 0.f;
#pragma unroll
    for (int j = 0; j < 9; j++) n2 += t[j] * t[j];
    float inv = 1.0f / (n2 + 1.0f);

    float xn[9];
    float* xnp = g_Xn + (size_t)idx * 9;
#pragma unroll
    for (int j = 0; j < 9; j++) { xn[j] = t[j] * inv; xnp[j] = xn[j]; }

    float i0 = (xn[0] + xn[4] + xn[8]) * (1.0f / 3.0f);
    sp[nl][0][c] = i0;
    sp[nl][1][c] = 0.5f * (xn[1] - xn[3]);
    sp[nl][2][c] = 0.5f * (xn[2] - xn[6]);
    sp[nl][3][c] = 0.5f * (xn[5] - xn[7]);
    sp[nl][4][c] = xn[0] - i0;
    sp[nl][5][c] = xn[4] - i0;
    sp[nl][6][c] = 0.5f * (xn[1] + xn[3]);
    sp[nl][7][c] = 0.5f * (xn[2] + xn[6]);
    sp[nl][8][c] = 0.5f * (xn[5] + xn[7]);
    __syncthreads();

    float acc[9];
#pragma unroll
    for (int j = 0; j < 9; j++) acc[j] = 0.f;
    for (int k = 0; k < CC; k++) {
        float w0 = __ldg(Wt +        k * CC + c);
        float w1 = __ldg(Wt + 4096 + k * CC + c);
        float w2 = __ldg(Wt + 8192 + k * CC + c);
        acc[0] += sp[nl][0][k] * w0;
        acc[1] += sp[nl][1][k] * w1;
        acc[2] += sp[nl][2][k] * w1;
        acc[3] += sp[nl][3][k] * w1;
        acc[4] += sp[nl][4][k] * w2;
        acc[5] += sp[nl][5][k] * w2;
        acc[6] += sp[nl][6][k] * w2;
        acc[7] += sp[nl][7][k] * w2;
        acc[8] += sp[nl][8][k] * w2;
    }
    g_mixv[idx]          = make_float4(acc[0], acc[1], acc[2], acc[3]);
    g_mixv[NC + idx]     = make_float4(acc[4], acc[5], acc[6], acc[7]);
    g_mixv[2 * NC + idx] = make_float4(acc[8], 0.f, 0.f, 0.f);
}

// ================= CSR build =================
__global__ void k_hist(const int* __restrict__ ei) {
    int e = blockIdx.x * 256 + threadIdx.x;
    if (e < EE) atomicAdd(&g_cnt[__ldg(ei + e)], 1);
}

__global__ void k_scan() {
    int t = threadIdx.x;
    int base = t * 10;
    int loc[10];
    int s = 0;
#pragma unroll
    for (int i = 0; i < 10; i++) {
        int nn = base + i;
        int v = (nn < NN) ? g_cnt[nn] : 0;
        loc[i] = s; s += v;
    }
    __shared__ int smv[1024];
    smv[t] = s;
    __syncthreads();
    for (int off = 1; off < 1024; off <<= 1) {
        int v = (t >= off) ? smv[t - off] : 0;
        __syncthreads();
        smv[t] += v;
        __syncthreads();
    }
    int pre = (t > 0) ? smv[t - 1] : 0;
#pragma unroll
    for (int i = 0; i < 10; i++) {
        int nn = base + i;
        if (nn < NN) { int o = pre + loc[i]; g_off[nn] = o; g_cnt[nn] = o; }
    }
    if (t == 1023) g_off[NN] = smv[1023];
}

__global__ void k_fill(const int* __restrict__ ei) {
    int e = blockIdx.x * 256 + threadIdx.x;
    if (e < EE) {
        int src = __ldg(ei + e);
        int dst = __ldg(ei + EE + e);
        int pos = atomicAdd(&g_cnt[src], 1);
        g_el[pos] = make_int2(e, dst);
    }
}

// ================= Kernel B: fused edge MLP, 256 threads, edge-QUAD blocking ==========
// smem float offsets (identical layout to the passing R10 kernel)
#define SW2 0          // 64*128  = 8192
#define SW3 8192       // 128*192 = 24576  -> ends 32768
#define SH2 32768      // 128 x 128 = 16384 -> ends 49152 (W1 overlays start, dead after L1)
#define SW1 32768      // 32*64 = 2048
#define SH1 49152      // 64 x 128 = 8192  -> ends 57344 (ea staging + h1)
#define SBUF 49152     // overlay of SH1 after layer2: [128][66] = 8448 -> ends 57600
#define SMEM_FLOATS 57600

__global__ void __launch_bounds__(256, 1) k_mlp(
    const float* __restrict__ ea, const float* __restrict__ ew,
    const float* __restrict__ W1, const float* __restrict__ b1,
    const float* __restrict__ W2, const float* __restrict__ b2,
    const float* __restrict__ W3, const float* __restrict__ b3)
{
    extern __shared__ float sm[];
    int tid = threadIdx.x;
    int quad = tid & 31;      // edge quad -> edges e0 = 4*quad .. e0+3
    int sl = tid >> 5;        // output slice 0..7 (uniform per warp)
    int e0 = 4 * quad;

    // ---- cooperative staging ----
    {
        float4* d; const float4* s;
        d = (float4*)(sm + SW2); s = (const float4*)W2;
        for (int i = tid; i < 2048; i += 256) d[i] = s[i];
        d = (float4*)(sm + SW3); s = (const float4*)W3;
        for (int i = tid; i < 6144; i += 256) d[i] = s[i];
        d = (float4*)(sm + SW1); s = (const float4*)W1;
        for (int i = tid; i < 512; i += 256) d[i] = s[i];
        // edge_attr [128 edges][32] -> sm[SH1 + r*128 + e_local]
        const float4* g = (const float4*)(ea + (size_t)blockIdx.x * 128 * 32);
        for (int i = tid; i < 1024; i += 256) {
            float4 v = g[i];
            int el = i >> 3, r0 = (i & 7) * 4;
            sm[SH1 + (r0 + 0) * 128 + el] = v.x;
            sm[SH1 + (r0 + 1) * 128 + el] = v.y;
            sm[SH1 + (r0 + 2) * 128 + el] = v.z;
            sm[SH1 + (r0 + 3) * 128 + el] = v.w;
        }
    }
    __syncthreads();

    unsigned long long acc2[32];   // up to 8 pairs x 4 edges (layer 2)

    // ---- layer 1: 32 -> 64; outputs [sl*8, sl*8+8) (4 pairs) for 4 edges ----
    {
        const float* bp = b1 + sl * 8;
        unsigned long long binit[4];
#pragma unroll
        for (int j = 0; j < 4; j++) {
            unsigned lo = __float_as_uint(__ldg(bp + 2 * j));
            unsigned hi = __float_as_uint(__ldg(bp + 2 * j + 1));
            PACK2(binit[j], lo, hi);
        }
#pragma unroll
        for (int e = 0; e < 4; e++)
#pragma unroll
            for (int j = 0; j < 4; j++) acc2[e * 4 + j] = binit[j];
        for (int r = 0; r < 32; r++) {
            float4 xv = *(float4*)(sm + SH1 + r * 128 + e0);
            unsigned long long xd[4];
            { unsigned u = __float_as_uint(xv.x); PACK2(xd[0], u, u); }
            { unsigned u = __float_as_uint(xv.y); PACK2(xd[1], u, u); }
            { unsigned u = __float_as_uint(xv.z); PACK2(xd[2], u, u); }
            { unsigned u = __float_as_uint(xv.w); PACK2(xd[3], u, u); }
            const ulonglong2* wr = (const ulonglong2*)(sm + SW1 + r * 64 + sl * 8);
#pragma unroll
            for (int q = 0; q < 2; q++) {
                ulonglong2 w = wr[q];
#pragma unroll
                for (int e = 0; e < 4; e++) {
                    FMA2(acc2[e * 4 + 2 * q],     xd[e], w.x, acc2[e * 4 + 2 * q]);
                    FMA2(acc2[e * 4 + 2 * q + 1], xd[e], w.y, acc2[e * 4 + 2 * q + 1]);
                }
            }
        }
    }
    __syncthreads();   // all ea reads done before h1 overwrites SH1
#pragma unroll
    for (int j = 0; j < 4; j++) {
        float4 v0, v1;   // output rows sl*8+2j, sl*8+2j+1 across 4 edges
        unsigned l0, h0, l1, h1, l2, h2, l3, h3;
        UNPACK2(l0, h0, acc2[0 * 4 + j]);
        UNPACK2(l1, h1, acc2[1 * 4 + j]);
        UNPACK2(l2, h2, acc2[2 * 4 + j]);
        UNPACK2(l3, h3, acc2[3 * 4 + j]);
        v0 = make_float4(silu_f(__uint_as_float(l0)), silu_f(__uint_as_float(l1)),
                         silu_f(__uint_as_float(l2)), silu_f(__uint_as_float(l3)));
        v1 = make_float4(silu_f(__uint_as_float(h0)), silu_f(__uint_as_float(h1)),
                         silu_f(__uint_as_float(h2)), silu_f(__uint_as_float(h3)));
        *(float4*)(sm + SH1 + (sl * 8 + 2 * j)     * 128 + e0) = v0;
        *(float4*)(sm + SH1 + (sl * 8 + 2 * j + 1) * 128 + e0) = v1;
    }
    __syncthreads();   // h1 complete; W1 reads done before h2 clobbers SW1 region

    // ---- layer 2: 64 -> 128; outputs [sl*16, sl*16+16) (8 pairs) for 4 edges ----
    {
        const float* bp = b2 + sl * 16;
        unsigned long long binit[8];
#pragma unroll
        for (int j = 0; j < 8; j++) {
            unsigned lo = __float_as_uint(__ldg(bp + 2 * j));
            unsigned hi = __float_as_uint(__ldg(bp + 2 * j + 1));
            PACK2(binit[j], lo, hi);
        }
#pragma unroll
        for (int e = 0; e < 4; e++)
#pragma unroll
            for (int j = 0; j < 8; j++) acc2[e * 8 + j] = binit[j];
        for (int k = 0; k < 64; k++) {
            float4 xv = *(float4*)(sm + SH1 + k * 128 + e0);
            unsigned long long xd[4];
            { unsigned u = __float_as_uint(xv.x); PACK2(xd[0], u, u); }
            { unsigned u = __float_as_uint(xv.y); PACK2(xd[1], u, u); }
            { unsigned u = __float_as_uint(xv.z); PACK2(xd[2], u, u); }
            { unsigned u = __float_as_uint(xv.w); PACK2(xd[3], u, u); }
            const ulonglong2* wr = (const ulonglong2*)(sm + SW2 + k * 128 + sl * 16);
#pragma unroll
            for (int q = 0; q < 4; q++) {
                ulonglong2 w = wr[q];
#pragma unroll
                for (int e = 0; e < 4; e++) {
                    FMA2(acc2[e * 8 + 2 * q],     xd[e], w.x, acc2[e * 8 + 2 * q]);
                    FMA2(acc2[e * 8 + 2 * q + 1], xd[e], w.y, acc2[e * 8 + 2 * q + 1]);
                }
            }
        }
    }
    // h2 -> SH2 (overlays dead W1); layer-2 readers touch SH1/SW2 only. Safe without barrier here.
#pragma unroll
    for (int j = 0; j < 8; j++) {
        unsigned l0, h0, l1, h1, l2, h2, l3, h3;
        UNPACK2(l0, h0, acc2[0 * 8 + j]);
        UNPACK2(l1, h1, acc2[1 * 8 + j]);
        UNPACK2(l2, h2, acc2[2 * 8 + j]);
        UNPACK2(l3, h3, acc2[3 * 8 + j]);
        *(float4*)(sm + SH2 + (sl * 16 + 2 * j)     * 128 + e0) =
            make_float4(silu_f(__uint_as_float(l0)), silu_f(__uint_as_float(l1)),
                        silu_f(__uint_as_float(l2)), silu_f(__uint_as_float(l3)));
        *(float4*)(sm + SH2 + (sl * 16 + 2 * j + 1) * 128 + e0) =
            make_float4(silu_f(__uint_as_float(h0)), silu_f(__uint_as_float(h1)),
                        silu_f(__uint_as_float(h2)), silu_f(__uint_as_float(h3)));
    }
    __syncthreads();   // h2 complete; SH1 dead -> SBUF usable

    // ---- cutoff (4 edges) ----
    int eg0 = blockIdx.x * 128 + e0;
    float4 wv = __ldg((const float4*)(ew + eg0));
    float cw[4];
    cw[0] = (wv.x < CUT) ? 0.5f * (cosf(wv.x * (float)(M_PI / 5.0)) + 1.0f) : 0.0f;
    cw[1] = (wv.y < CUT) ? 0.5f * (cosf(wv.y * (float)(M_PI / 5.0)) + 1.0f) : 0.0f;
    cw[2] = (wv.z < CUT) ? 0.5f * (cosf(wv.z * (float)(M_PI / 5.0)) + 1.0f) : 0.0f;
    cw[3] = (wv.w < CUT) ? 0.5f * (cosf(wv.w * (float)(M_PI / 5.0)) + 1.0f) : 0.0f;

    // ---- layer 3: 128 -> 192, 3 chunks; outputs [oc*64 + sl*8, +8) for 4 edges ----
#pragma unroll 1
    for (int oc = 0; oc < 3; oc++) {
        const float* bp = b3 + oc * 64 + sl * 8;
        unsigned long long binit[4];
#pragma unroll
        for (int j = 0; j < 4; j++) {
            unsigned lo = __float_as_uint(__ldg(bp + 2 * j));
            unsigned hi = __float_as_uint(__ldg(bp + 2 * j + 1));
            PACK2(binit[j], lo, hi);
        }
#pragma unroll
        for (int e = 0; e < 4; e++)
#pragma unroll
            for (int j = 0; j < 4; j++) acc2[e * 4 + j] = binit[j];
        for (int k = 0; k < 128; k++) {
            float4 xv = *(float4*)(sm + SH2 + k * 128 + e0);
            unsigned long long xd[4];
            { unsigned u = __float_as_uint(xv.x); PACK2(xd[0], u, u); }
            { unsigned u = __float_as_uint(xv.y); PACK2(xd[1], u, u); }
            { unsigned u = __float_as_uint(xv.z); PACK2(xd[2], u, u); }
            { unsigned u = __float_as_uint(xv.w); PACK2(xd[3], u, u); }
            const ulonglong2* wr = (const ulonglong2*)(sm + SW3 + k * 192 + oc * 64 + sl * 8);
#pragma unroll
            for (int q = 0; q < 2; q++) {
                ulonglong2 w = wr[q];
#pragma unroll
                for (int e = 0; e < 4; e++) {
                    FMA2(acc2[e * 4 + 2 * q],     xd[e], w.x, acc2[e * 4 + 2 * q]);
                    FMA2(acc2[e * 4 + 2 * q + 1], xd[e], w.y, acc2[e * 4 + 2 * q + 1]);
                }
            }
        }
        // silu * cw -> sbuf[e][o] (row stride 66)
#pragma unroll
        for (int e = 0; e < 4; e++) {
#pragma unroll
            for (int j = 0; j < 4; j++) {
                unsigned lo, hi;
                UNPACK2(lo, hi, acc2[e * 4 + j]);
                int ob = sl * 8 + 2 * j;
                sm[SBUF + (e0 + e) * 66 + ob]     = silu_f(__uint_as_float(lo)) * cw[e];
                sm[SBUF + (e0 + e) * 66 + ob + 1] = silu_f(__uint_as_float(hi)) * cw[e];
            }
        }
        __syncthreads();
        // coalesced store: float2 sweep of columns
        for (int i = tid; i < 4096; i += 256) {
            int el2 = i >> 5, c2 = (i & 31) * 2;
            float2 v = *(float2*)(sm + SBUF + el2 * 66 + c2);
            *(float2*)(g_af + (size_t)(blockIdx.x * 128 + el2) * 192 + oc * 64 + c2) = v;
        }
        __syncthreads();
    }
}

// ================= Kernel C: CSR gather + accumulate, 4 edge-slices =============
__global__ void k_msg(void) {
    int n = blockIdx.x;
    int tid = threadIdx.x;
    int s = tid >> 6, c = tid & 63;
    __shared__ float red[3][64][13];

    int i0 = g_off[n], i1 = g_off[n + 1];
    float a0v0 = 0.f, a0v1 = 0.f, a0v2 = 0.f, a0v3 = 0.f;
    float a1v0 = 0.f, a1v1 = 0.f, a1v2 = 0.f, a1v3 = 0.f;
    float a2v = 0.f;
    for (int i = i0 + s; i < i1; i += 4) {
        int2 cur = __ldg(&g_el[i]);
        const float* ap = g_af + (size_t)cur.x * 192 + c * 3;
        float a0 = __ldg(ap), a1 = __ldg(ap + 1), a2 = __ldg(ap + 2);
        int mi = cur.y * CC + c;
        float4 m0 = __ldg(&g_mixv[mi]);
        float4 m1 = __ldg(&g_mixv[NC + mi]);
        float4 m2 = __ldg(&g_mixv[2 * NC + mi]);
        a0v0 += a0 * m0.x; a0v1 += a1 * m0.y; a0v2 += a1 * m0.z; a0v3 += a1 * m0.w;
        a1v0 += a2 * m1.x; a1v1 += a2 * m1.y; a1v2 += a2 * m1.z; a1v3 += a2 * m1.w;
        a2v  += a2 * m2.x;
    }
    if (s > 0) {
        float* rp = red[s - 1][c];
        rp[0] = a0v0; rp[1] = a0v1; rp[2] = a0v2; rp[3] = a0v3;
        rp[4] = a1v0; rp[5] = a1v1; rp[6] = a1v2; rp[7] = a1v3;
        rp[8] = a2v;
    }
    __syncthreads();
    if (s == 0) {
#pragma unroll
        for (int ss = 0; ss < 3; ss++) {
            float* rp = red[ss][c];
            a0v0 += rp[0]; a0v1 += rp[1]; a0v2 += rp[2]; a0v3 += rp[3];
            a1v0 += rp[4]; a1v1 += rp[5]; a1v2 += rp[6]; a1v3 += rp[7];
            a2v  += rp[8];
        }
        int idx = n * CC + c;
        g_msgv[idx]          = make_float4(a0v0, a0v1, a0v2, a0v3);
        g_msgv[NC + idx]     = make_float4(a1v0, a1v1, a1v2, a1v3);
        g_msgv[2 * NC + idx] = make_float4(a2v, 0.f, 0.f, 0.f);
    }
}

// ================= Kernel D: combine, second decomposition+mix, output ==================
__global__ void k_out(const float* __restrict__ Wt, float* __restrict__ out) {
    int tid = threadIdx.x;
    int nl = tid >> 6, c = tid & 63;
    int n = blockIdx.x * 4 + nl;
    __shared__ float sp[4][9][CC];

    int idx = n * CC + c;
    float4 g0 = g_msgv[idx], g1 = g_msgv[NC + idx], g2 = g_msgv[2 * NC + idx];
    float4 y0 = g_mixv[idx], y1 = g_mixv[NC + idx], y2 = g_mixv[2 * NC + idx];
    float m9[9] = { g0.x, g0.y, g0.z, g0.w, g1.x, g1.y, g1.z, g1.w, g2.x };
    float y9[9] = { y0.x, y0.y, y0.z, y0.w, y1.x, y1.y, y1.z, y1.w, y2.x };

    float Mg[3][3] = {
        { m9[0]+m9[4],  m9[1]+m9[6],  m9[2]+m9[7] },
        { m9[6]-m9[1],  m9[0]+m9[5],  m9[3]+m9[8] },
        { m9[7]-m9[2],  m9[8]-m9[3],  m9[0]-m9[4]-m9[5] }
    };
    float Yf[3][3] = {
        { y9[0]+y9[4],  y9[1]+y9[6],  y9[2]+y9[7] },
        { y9[6]-y9[1],  y9[0]+y9[5],  y9[3]+y9[8] },
        { y9[7]-y9[2],  y9[8]-y9[3],  y9[0]-y9[4]-y9[5] }
    };

    float M[3][3];
#pragma unroll
    for (int i = 0; i < 3; i++)
#pragma unroll
        for (int j = 0; j < 3; j++) {
            float sacc = 0.f;
#pragma unroll
            for (int k = 0; k < 3; k++)
                sacc += Mg[i][k] * Yf[k][j] + Yf[i][k] * Mg[k][j];
            M[i][j] = sacc;
        }

    float tn = 0.f;
#pragma unroll
    for (int i = 0; i < 3; i++)
#pragma unroll
        for (int j = 0; j < 3; j++) tn += M[i][j] * M[i][j];
    float inv = 1.0f / (tn + 1.0f);

    float i0 = (M[0][0] + M[1][1] + M[2][2]) * (1.0f / 3.0f);
    sp[nl][0][c] = i0 * inv;
    sp[nl][1][c] = 0.5f * (M[0][1] - M[1][0]) * inv;
    sp[nl][2][c] = 0.5f * (M[0][2] - M[2][0]) * inv;
    sp[nl][3][c] = 0.5f * (M[1][2] - M[2][1]) * inv;
    sp[nl][4][c] = (M[0][0] - i0) * inv;
    sp[nl][5][c] = (M[1][1] - i0) * inv;
    sp[nl][6][c] = 0.5f * (M[0][1] + M[1][0]) * inv;
    sp[nl][7][c] = 0.5f * (M[0][2] + M[2][0]) * inv;
    sp[nl][8][c] = 0.5f * (M[1][2] + M[2][1]) * inv;
    __syncthreads();

    float acc[9];
#pragma unroll
    for (int j = 0; j < 9; j++) acc[j] = 0.f;
    for (int k = 0; k < CC; k++) {
        float w3 = __ldg(Wt + 3*4096 + k * CC + c);
        float w4 = __ldg(Wt + 4*4096 + k * CC + c);
        float w5 = __ldg(Wt + 5*4096 + k * CC + c);
        acc[0] += sp[nl][0][k] * w3;
        acc[1] += sp[nl][1][k] * w4;
        acc[2] += sp[nl][2][k] * w4;
        acc[3] += sp[nl][3][k] * w4;
        acc[4] += sp[nl][4][k] * w5;
        acc[5] += sp[nl][5][k] * w5;
        acc[6] += sp[nl][6][k] * w5;
        acc[7] += sp[nl][7][k] * w5;
        acc[8] += sp[nl][8][k] * w5;
    }

    float D[3][3] = {
        { acc[0]+acc[4],  acc[1]+acc[6],  acc[2]+acc[7] },
        { acc[6]-acc[1],  acc[0]+acc[5],  acc[3]+acc[8] },
        { acc[7]-acc[2],  acc[8]-acc[3],  acc[0]-acc[4]-acc[5] }
    };
    float D2[3][3];
#pragma unroll
    for (int i = 0; i < 3; i++)
#pragma unroll
        for (int j = 0; j < 3; j++) {
            float sacc = 0.f;
#pragma unroll
            for (int k = 0; k < 3; k++) sacc += D[i][k] * D[k][j];
            D2[i][j] = sacc;
        }

    const float* xnp = g_Xn + (size_t)idx * 9;
    float* op = out + (size_t)idx * 9;
#pragma unroll
    for (int i = 0; i < 3; i++)
#pragma unroll
        for (int j = 0; j < 3; j++)
            op[3*i+j] = xnp[3*i+j] + D[i][j] + D2[i][j];
}

// ======================= launch =======================
extern "C" void kernel_launch(void* const* d_in, const int* in_sizes, int n_in,
                              void* d_out, int out_size) {
    const float* X  = (const float*)d_in[0];
    const int*   ei = (const int*)  d_in[1];
    const float* ew = (const float*)d_in[2];
    const float* ea = (const float*)d_in[3];
    const float* W1 = (const float*)d_in[4];
    const float* b1 = (const float*)d_in[5];
    const float* W2 = (const float*)d_in[6];
    const float* b2 = (const float*)d_in[7];
    const float* W3 = (const float*)d_in[8];
    const float* b3 = (const float*)d_in[9];
    const float* Wt = (const float*)d_in[10];

    const int smem_bytes = SMEM_FLOATS * 4;   // 230400
    cudaFuncSetAttribute(k_mlp, cudaFuncAttributeMaxDynamicSharedMemorySize, smem_bytes);

    k_node<<<NN / 4, 256>>>(X, Wt);
    k_hist<<<(EE + 255) / 256, 256>>>(ei);
    k_scan<<<1, 1024>>>();
    k_mlp<<<EE / 128, 256, smem_bytes>>>(ea, ew, W1, b1, W2, b2, W3, b3);   // 4th launch -> profiled
    k_fill<<<(EE + 255) / 256, 256>>>(ei);
    k_msg<<<NN, 256>>>();
    k_out<<<NN / 4, 256>>>(Wt, (float*)d_out);
}